// round 5
// baseline (speedup 1.0000x reference)
#include <cuda_runtime.h>
#include <cstdint>

// Problem constants
#define Bc 4
#define Nc 8192
#define Cc 64
#define Kc 16
#define PPC 32            // points per CTA in block kernel
#define BNS 0.99999500003749968f   // 1/sqrt(1+1e-5)

// folded-weight layout (floats) per block
#define FW1  0            // [3][64]  col-major-ish [c*64+o]
#define FW2  192          // [64][64] [c*64+o]
#define FWA1 (192+4096)
#define FWA2 (192+8192)
#define FWD  (192+12288)
#define FB1  (192+16384)
#define FB2  (FB1+64)
#define FB3  (FB1+128)
#define FB4  (FB1+192)
#define FBD  (FB1+256)
#define FOLD_SZ (FB1+320) // 16896 floats

// smem extras beyond folded block
#define SM_FLOATS (FOLD_SZ + 48 + 1088 + 1088 + 64)
#define SMEM_BYTES (SM_FLOATS*4 + 16*4)   // + sIdx (16 ints) = 76800 B

// ---------------- device scratch (no allocation allowed) ----------------
__device__ float g_pt[Bc*Nc*3];        // p transposed (B,N,3)
__device__ float g_xa[Bc*Nc*Cc];       // x ping (B,N,C)
__device__ float g_xb[Bc*Nc*Cc];       // x pong (B,N,C)
__device__ float g_fold[2*FOLD_SZ];    // folded weights/biases per block

// ---------------- fold BN into weights/biases ----------------
__global__ void fold_kernel(
    const float* __restrict__ dw1, const float* __restrict__ db1,
    const float* __restrict__ dg1, const float* __restrict__ dbe1,
    const float* __restrict__ dw2, const float* __restrict__ db2,
    const float* __restrict__ dg2, const float* __restrict__ dbe2,
    const float* __restrict__ aw1, const float* __restrict__ ab1,
    const float* __restrict__ ag1, const float* __restrict__ abe1,
    const float* __restrict__ aw2, const float* __restrict__ ab2,
    const float* __restrict__ ag2, const float* __restrict__ abe2,
    const float* __restrict__ lw,  const float* __restrict__ lb,
    const float* __restrict__ lg,  const float* __restrict__ lbe)
{
    const int blk = blockIdx.x;
    float* F = g_fold + blk*FOLD_SZ;
    const int tid = threadIdx.x;

    for (int t = tid; t < 192; t += 256) {
        int c = t >> 6, o = t & 63;
        F[FW1 + t] = dw1[blk*Cc*3 + o*3 + c] * dg1[blk*Cc + o] * BNS;
    }
    for (int t = tid; t < 4096; t += 256) {
        int c = t >> 6, o = t & 63;
        int g = o*64 + c;
        F[FW2  + t] = dw2[blk*4096 + g] * dg2[blk*Cc + o] * BNS;
        F[FWA1 + t] = aw1[blk*4096 + g] * ag1[blk*Cc + o] * BNS;
        F[FWA2 + t] = aw2[blk*4096 + g] * ag2[blk*Cc + o] * BNS;
        F[FWD  + t] = lw [blk*4096 + g] * lg [blk*Cc + o] * BNS;
    }
    for (int o = tid; o < 64; o += 256) {
        F[FB1+o] = db1[blk*Cc+o]*dg1[blk*Cc+o]*BNS + dbe1[blk*Cc+o];
        F[FB2+o] = db2[blk*Cc+o]*dg2[blk*Cc+o]*BNS + dbe2[blk*Cc+o];
        F[FB3+o] = ab1[blk*Cc+o]*ag1[blk*Cc+o]*BNS + abe1[blk*Cc+o];
        F[FB4+o] = ab2[blk*Cc+o]*ag2[blk*Cc+o]*BNS + abe2[blk*Cc+o];
        F[FBD+o] = lb [blk*Cc+o]*lg [blk*Cc+o]*BNS + lbe [blk*Cc+o];
    }
}

// ---------------- transposes ----------------
__global__ void transpose_p_kernel(const float* __restrict__ pin)
{
    int t = blockIdx.x*blockDim.x + threadIdx.x;     // over B*N
    if (t >= Bc*Nc) return;
    int b = t >> 13, n = t & (Nc-1);
    #pragma unroll
    for (int c = 0; c < 3; c++)
        g_pt[t*3 + c] = pin[((size_t)b*3 + c)*Nc + n];
}

__global__ void transpose_in_kernel(const float* __restrict__ src)
{
    // src (B,C,N) -> g_xa (B,N,C)
    __shared__ float tile[32][33];
    int b  = blockIdx.z;
    int n0 = blockIdx.x * 32;
    int c0 = blockIdx.y * 32;
    int tx = threadIdx.x, ty = threadIdx.y;
    #pragma unroll
    for (int i = 0; i < 32; i += 8)
        tile[ty+i][tx] = src[((size_t)b*Cc + c0+ty+i)*Nc + n0 + tx];
    __syncthreads();
    #pragma unroll
    for (int i = 0; i < 32; i += 8)
        g_xa[((size_t)b*Nc + n0+ty+i)*Cc + c0 + tx] = tile[tx][ty+i];
}

__global__ void transpose_out_kernel(float* __restrict__ dst)
{
    // g_xa (B,N,C) -> dst (B,C,N)
    __shared__ float tile[32][33];
    int b  = blockIdx.z;
    int n0 = blockIdx.x * 32;
    int c0 = blockIdx.y * 32;
    int tx = threadIdx.x, ty = threadIdx.y;
    #pragma unroll
    for (int i = 0; i < 32; i += 8)
        tile[ty+i][tx] = g_xa[((size_t)b*Nc + n0+ty+i)*Cc + c0 + tx];
    __syncthreads();
    #pragma unroll
    for (int i = 0; i < 32; i += 8)
        dst[((size_t)b*Cc + c0+ty+i)*Nc + n0 + tx] = tile[tx][ty+i];
}

// ---------------- fused block kernel ----------------
__global__ void __launch_bounds__(256, 2)
block_kernel(const int* __restrict__ idxg, int blk, int dir)
{
    const float* __restrict__ xin  = dir ? g_xb : g_xa;
    float*       __restrict__ xout = dir ? g_xa : g_xb;

    extern __shared__ float sm[];
    const int tid = threadIdx.x;

    // load folded weights/biases coalesced
    {
        const float* F = g_fold + blk*FOLD_SZ;
        for (int t = tid; t < FOLD_SZ; t += 256) sm[t] = F[t];
    }
    float* sRel = sm + FOLD_SZ;      // [3][16]
    float* sA   = sRel + 48;         // [64][17]
    float* sBb  = sA + 1088;         // [64][17]
    float* sY   = sBb + 1088;        // [64]
    int*   sIdx = (int*)(sY + 64);   // [16]
    __syncthreads();

    const int j  = tid >> 4;    // neighbor column 0..15
    const int og = tid & 15;
    const int ob = og * 4;      // 4 output channels per thread

    for (int pi = 0; pi < PPC; ++pi) {
        const int gp = blockIdx.x * PPC + pi;   // = b*N + n
        const int b  = gp >> 13;

        if (tid < 16) {
            int nb = idxg[gp*Kc + tid];
            sIdx[tid] = nb;
            const float* pc = g_pt + (size_t)gp*3;
            const float* pn = g_pt + ((size_t)b*Nc + nb)*3;
            sRel[tid]      = pc[0] - pn[0];
            sRel[16+tid]   = pc[1] - pn[1];
            sRel[32+tid]   = pc[2] - pn[2];
        }
        __syncthreads();

        // prefetch gathered features + residual (hide latency under GEMMs)
        float4 gx = *reinterpret_cast<const float4*>(
            xin + ((size_t)b*Nc + sIdx[j])*Cc + ob);
        float resv = 0.f;
        if (tid < 64) resv = xin[(size_t)gp*Cc + tid];

        float acc[4];

        // ---- delta layer1: 64x3, relu(bn) ----
        #pragma unroll
        for (int i = 0; i < 4; i++) acc[i] = sm[FB1 + ob + i];
        #pragma unroll
        for (int c = 0; c < 3; c++) {
            float rv = sRel[c*16 + j];
            #pragma unroll
            for (int i = 0; i < 4; i++)
                acc[i] = fmaf(sm[FW1 + c*64 + ob + i], rv, acc[i]);
        }
        #pragma unroll
        for (int i = 0; i < 4; i++) sA[(ob+i)*17 + j] = fmaxf(acc[i], 0.f);
        __syncthreads();

        // ---- delta layer2: 64x64, bn (no relu), + gathered x ----
        #pragma unroll
        for (int i = 0; i < 4; i++) acc[i] = sm[FB2 + ob + i];
        #pragma unroll
        for (int c = 0; c < 64; c++) {
            float av = sA[c*17 + j];
            float4 w = *reinterpret_cast<const float4*>(&sm[FW2 + c*64 + ob]);
            acc[0] = fmaf(w.x, av, acc[0]);
            acc[1] = fmaf(w.y, av, acc[1]);
            acc[2] = fmaf(w.z, av, acc[2]);
            acc[3] = fmaf(w.w, av, acc[3]);
        }
        acc[0] += gx.x; acc[1] += gx.y; acc[2] += gx.z; acc[3] += gx.w;
        #pragma unroll
        for (int i = 0; i < 4; i++) sBb[(ob+i)*17 + j] = acc[i];
        __syncthreads();

        // ---- alpha layer1: 64x64, relu(bn) ----
        #pragma unroll
        for (int i = 0; i < 4; i++) acc[i] = sm[FB3 + ob + i];
        #pragma unroll
        for (int c = 0; c < 64; c++) {
            float av = sBb[c*17 + j];
            float4 w = *reinterpret_cast<const float4*>(&sm[FWA1 + c*64 + ob]);
            acc[0] = fmaf(w.x, av, acc[0]);
            acc[1] = fmaf(w.y, av, acc[1]);
            acc[2] = fmaf(w.z, av, acc[2]);
            acc[3] = fmaf(w.w, av, acc[3]);
        }
        #pragma unroll
        for (int i = 0; i < 4; i++) sA[(ob+i)*17 + j] = fmaxf(acc[i], 0.f);
        __syncthreads();

        // ---- alpha layer2: 64x64, relu(bn) ----
        #pragma unroll
        for (int i = 0; i < 4; i++) acc[i] = sm[FB4 + ob + i];
        #pragma unroll
        for (int c = 0; c < 64; c++) {
            float av = sA[c*17 + j];
            float4 w = *reinterpret_cast<const float4*>(&sm[FWA2 + c*64 + ob]);
            acc[0] = fmaf(w.x, av, acc[0]);
            acc[1] = fmaf(w.y, av, acc[1]);
            acc[2] = fmaf(w.z, av, acc[2]);
            acc[3] = fmaf(w.w, av, acc[3]);
        }
        #pragma unroll
        for (int i = 0; i < 4; i++) sBb[(ob+i)*17 + j] = fmaxf(acc[i], 0.f);
        __syncthreads();

        // ---- max over K ----
        if (tid < 64) {
            float m = sBb[tid*17 + 0];
            #pragma unroll
            for (int jj = 1; jj < 16; jj++) m = fmaxf(m, sBb[tid*17 + jj]);
            sY[tid] = m;
        }
        __syncthreads();

        // ---- down: 64x64 bn + residual ----
        if (tid < 64) {
            float o = sm[FBD + tid];
            #pragma unroll
            for (int c = 0; c < 64; c++)
                o = fmaf(sm[FWD + c*64 + tid], sY[c], o);
            xout[(size_t)gp*Cc + tid] = o + resv;
        }
        __syncthreads();
    }
}

// ---------------- launch ----------------
extern "C" void kernel_launch(void* const* d_in, const int* in_sizes, int n_in,
                              void* d_out, int out_size)
{
    const float* input_p = (const float*)d_in[0];
    const float* input_x = (const float*)d_in[1];
    const int*   idx     = (const int*)  d_in[2];
    const float* P[20];
    for (int i = 0; i < 20; i++) P[i] = (const float*)d_in[3 + i];
    float* out = (float*)d_out;

    cudaFuncSetAttribute(block_kernel,
        cudaFuncAttributeMaxDynamicSharedMemorySize, SMEM_BYTES);

    fold_kernel<<<2, 256>>>(P[0],P[1],P[2],P[3], P[4],P[5],P[6],P[7],
                            P[8],P[9],P[10],P[11], P[12],P[13],P[14],P[15],
                            P[16],P[17],P[18],P[19]);
    transpose_p_kernel<<<(Bc*Nc + 255)/256, 256>>>(input_p);
    {
        dim3 tb(32, 8), tg(Nc/32, Cc/32, Bc);
        transpose_in_kernel<<<tg, tb>>>(input_x);
    }
    block_kernel<<<(Bc*Nc)/PPC, 256, SMEM_BYTES>>>(idx, 0, 0); // xa -> xb
    block_kernel<<<(Bc*Nc)/PPC, 256, SMEM_BYTES>>>(idx, 1, 1); // xb -> xa
    {
        dim3 tb(32, 8), tg(Nc/32, Cc/32, Bc);
        transpose_out_kernel<<<tg, tb>>>(out + Bc*3*Nc);
    }
    cudaMemcpyAsync(out, input_p, (size_t)Bc*3*Nc*sizeof(float),
                    cudaMemcpyDeviceToDevice);
}

// round 6
// speedup vs baseline: 2.8742x; 2.8742x over previous
#include <cuda_runtime.h>
#include <cstdint>

// Problem constants
#define Bc 4
#define Nc 8192
#define Cc 64
#define Kc 16
#define PPC 32            // points per CTA
#define PTS 4             // points in flight per CTA
#define BNS 0.99999500003749968f   // 1/sqrt(1+1e-5)

// folded-weight layout (floats) per block
#define FW1  0            // [3][64]  [c*64+o]
#define FW2  192          // [64][64] [c*64+o]
#define FWA1 (192+4096)
#define FWA2 (192+8192)
#define FWD  (192+12288)
#define FB1  (192+16384)
#define FB2  (FB1+64)
#define FB3  (FB1+128)
#define FB4  (FB1+192)
#define FBD  (FB1+256)
#define FOLD_SZ (FB1+320) // 16896 floats

// smem layout beyond weights (floats)
#define OFF_REL  FOLD_SZ                  // [4][3*16] = 192
#define OFF_A    (OFF_REL + 192)          // [4][64*16] = 4096
#define OFF_B    (OFF_A + 4096)           // [4][64*16] = 4096
#define OFF_Y    (OFF_B + 4096)           // [4][64] = 256
#define OFF_PART (OFF_Y + 256)            // [4][4*64] = 1024
#define OFF_IDX  (OFF_PART + 1024)        // [4][16] ints
#define SMEM_BYTES ((OFF_IDX + 64) * 4)   // 106496 B

// ---------------- device scratch ----------------
__device__ __align__(16) float g_pt[Bc*Nc*3];
__device__ __align__(16) float g_xa[Bc*Nc*Cc];
__device__ __align__(16) float g_xb[Bc*Nc*Cc];
__device__ __align__(16) float g_fold[2*FOLD_SZ];

// ---------------- packed f32x2 helpers ----------------
__device__ __forceinline__ unsigned long long ffma2(
    unsigned long long a, unsigned long long b, unsigned long long c) {
    unsigned long long d;
    asm("fma.rn.f32x2 %0, %1, %2, %3;" : "=l"(d) : "l"(a), "l"(b), "l"(c));
    return d;
}
__device__ __forceinline__ unsigned long long add2(
    unsigned long long a, unsigned long long b) {
    unsigned long long d;
    asm("add.rn.f32x2 %0, %1, %2;" : "=l"(d) : "l"(a), "l"(b));
    return d;
}
__device__ __forceinline__ unsigned long long pk2(float x) {
    unsigned long long r;
    asm("mov.b64 %0, {%1, %1};" : "=l"(r) : "f"(x));
    return r;
}
__device__ __forceinline__ unsigned long long pk2p(float x, float y) {
    unsigned long long r;
    asm("mov.b64 %0, {%1, %2};" : "=l"(r) : "f"(x), "f"(y));
    return r;
}
__device__ __forceinline__ float2 up2(unsigned long long v) {
    float2 f;
    asm("mov.b64 {%0, %1}, %2;" : "=f"(f.x), "=f"(f.y) : "l"(v));
    return f;
}
__device__ __forceinline__ unsigned long long relu2(unsigned long long v) {
    float2 f = up2(v);
    return pk2p(fmaxf(f.x, 0.f), fmaxf(f.y, 0.f));
}

// ---------------- fold BN into weights/biases ----------------
__global__ void fold_kernel(
    const float* __restrict__ dw1, const float* __restrict__ db1,
    const float* __restrict__ dg1, const float* __restrict__ dbe1,
    const float* __restrict__ dw2, const float* __restrict__ db2,
    const float* __restrict__ dg2, const float* __restrict__ dbe2,
    const float* __restrict__ aw1, const float* __restrict__ ab1,
    const float* __restrict__ ag1, const float* __restrict__ abe1,
    const float* __restrict__ aw2, const float* __restrict__ ab2,
    const float* __restrict__ ag2, const float* __restrict__ abe2,
    const float* __restrict__ lw,  const float* __restrict__ lb,
    const float* __restrict__ lg,  const float* __restrict__ lbe)
{
    const int blk = blockIdx.x;
    float* F = g_fold + blk*FOLD_SZ;
    const int tid = threadIdx.x;

    for (int t = tid; t < 192; t += 256) {
        int c = t >> 6, o = t & 63;
        F[FW1 + t] = dw1[blk*Cc*3 + o*3 + c] * dg1[blk*Cc + o] * BNS;
    }
    for (int t = tid; t < 4096; t += 256) {
        int c = t >> 6, o = t & 63;
        int g = o*64 + c;
        F[FW2  + t] = dw2[blk*4096 + g] * dg2[blk*Cc + o] * BNS;
        F[FWA1 + t] = aw1[blk*4096 + g] * ag1[blk*Cc + o] * BNS;
        F[FWA2 + t] = aw2[blk*4096 + g] * ag2[blk*Cc + o] * BNS;
        F[FWD  + t] = lw [blk*4096 + g] * lg [blk*Cc + o] * BNS;
    }
    for (int o = tid; o < 64; o += 256) {
        F[FB1+o] = db1[blk*Cc+o]*dg1[blk*Cc+o]*BNS + dbe1[blk*Cc+o];
        F[FB2+o] = db2[blk*Cc+o]*dg2[blk*Cc+o]*BNS + dbe2[blk*Cc+o];
        F[FB3+o] = ab1[blk*Cc+o]*ag1[blk*Cc+o]*BNS + abe1[blk*Cc+o];
        F[FB4+o] = ab2[blk*Cc+o]*ag2[blk*Cc+o]*BNS + abe2[blk*Cc+o];
        F[FBD+o] = lb [blk*Cc+o]*lg [blk*Cc+o]*BNS + lbe [blk*Cc+o];
    }
}

// ---------------- transposes ----------------
__global__ void transpose_p_kernel(const float* __restrict__ pin)
{
    int t = blockIdx.x*blockDim.x + threadIdx.x;
    if (t >= Bc*Nc) return;
    int b = t >> 13, n = t & (Nc-1);
    #pragma unroll
    for (int c = 0; c < 3; c++)
        g_pt[t*3 + c] = pin[((size_t)b*3 + c)*Nc + n];
}

__global__ void transpose_in_kernel(const float* __restrict__ src)
{
    __shared__ float tile[32][33];
    int b  = blockIdx.z;
    int n0 = blockIdx.x * 32;
    int c0 = blockIdx.y * 32;
    int tx = threadIdx.x, ty = threadIdx.y;
    #pragma unroll
    for (int i = 0; i < 32; i += 8)
        tile[ty+i][tx] = src[((size_t)b*Cc + c0+ty+i)*Nc + n0 + tx];
    __syncthreads();
    #pragma unroll
    for (int i = 0; i < 32; i += 8)
        g_xa[((size_t)b*Nc + n0+ty+i)*Cc + c0 + tx] = tile[tx][ty+i];
}

__global__ void transpose_out_kernel(float* __restrict__ dst)
{
    __shared__ float tile[32][33];
    int b  = blockIdx.z;
    int n0 = blockIdx.x * 32;
    int c0 = blockIdx.y * 32;
    int tx = threadIdx.x, ty = threadIdx.y;
    #pragma unroll
    for (int i = 0; i < 32; i += 8)
        tile[ty+i][tx] = g_xa[((size_t)b*Nc + n0+ty+i)*Cc + c0 + tx];
    __syncthreads();
    #pragma unroll
    for (int i = 0; i < 32; i += 8)
        dst[((size_t)b*Cc + c0+ty+i)*Nc + n0 + tx] = tile[tx][ty+i];
}

// 64-c GEMM accumulate: acc[o 0..3][jpair 0..1] over packed j-pairs.
__device__ __forceinline__ void gemm64(const float* __restrict__ W,
                                       const float* __restrict__ actIn,
                                       int jb, int ob,
                                       unsigned long long acc[4][2])
{
    #pragma unroll 16
    for (int c = 0; c < 64; ++c) {
        const int cg = ((jb ^ ((c >> 2) & 3)) << 2);
        ulonglong2 a = *reinterpret_cast<const ulonglong2*>(&actIn[c*16 + cg]);
        float4 w = *reinterpret_cast<const float4*>(&W[c*64 + ob]);
        unsigned long long w0 = pk2(w.x), w1 = pk2(w.y),
                           w2 = pk2(w.z), w3 = pk2(w.w);
        acc[0][0] = ffma2(w0, a.x, acc[0][0]);
        acc[0][1] = ffma2(w0, a.y, acc[0][1]);
        acc[1][0] = ffma2(w1, a.x, acc[1][0]);
        acc[1][1] = ffma2(w1, a.y, acc[1][1]);
        acc[2][0] = ffma2(w2, a.x, acc[2][0]);
        acc[2][1] = ffma2(w2, a.y, acc[2][1]);
        acc[3][0] = ffma2(w3, a.x, acc[3][0]);
        acc[3][1] = ffma2(w3, a.y, acc[3][1]);
    }
}

__device__ __forceinline__ void init_bias(const float* __restrict__ bias,
                                          int ob, unsigned long long acc[4][2])
{
    #pragma unroll
    for (int k = 0; k < 4; k++) {
        unsigned long long b = pk2(bias[ob + k]);
        acc[k][0] = b; acc[k][1] = b;
    }
}

__device__ __forceinline__ void store_act(float* __restrict__ out,
                                          int jb, int ob,
                                          unsigned long long acc[4][2],
                                          bool relu)
{
    const int cg = ((jb ^ ((ob >> 2) & 3)) << 2);   // row o: (o>>2)&3 == (ob>>2)&3
    #pragma unroll
    for (int k = 0; k < 4; k++) {
        unsigned long long v0 = acc[k][0], v1 = acc[k][1];
        if (relu) { v0 = relu2(v0); v1 = relu2(v1); }
        *reinterpret_cast<ulonglong2*>(&out[(ob + k)*16 + cg]) =
            make_ulonglong2(v0, v1);
    }
}

#define BARP() asm volatile("bar.sync %0, 64;" :: "r"(pp + 1) : "memory")

// ---------------- fused block kernel ----------------
__global__ void __launch_bounds__(256, 2)
block_kernel(const int* __restrict__ idxg, int blk, int dir)
{
    const float* __restrict__ xin  = dir ? g_xb : g_xa;
    float*       __restrict__ xout = dir ? g_xa : g_xb;

    extern __shared__ float sm[];
    const int tid = threadIdx.x;

    {   // load folded weights coalesced (float4)
        const float4* F4 = reinterpret_cast<const float4*>(g_fold + blk*FOLD_SZ);
        float4* S4 = reinterpret_cast<float4*>(sm);
        for (int t = tid; t < FOLD_SZ/4; t += 256) S4[t] = F4[t];
    }
    __syncthreads();

    const int pp = tid >> 6;          // point in flight 0..3
    const int t  = tid & 63;          // point-local thread
    const int jb = t >> 4;            // j-block 0..3
    const int og = t & 15;
    const int ob = og * 4;            // 4 output channels

    float* sRelP  = sm + OFF_REL  + pp*48;
    float* pA     = sm + OFF_A    + pp*1024;
    float* pB     = sm + OFF_B    + pp*1024;
    float* sYP    = sm + OFF_Y    + pp*64;
    float* sPartP = sm + OFF_PART + pp*256;
    int*   sIdxP  = (int*)(sm + OFF_IDX) + pp*16;

    for (int it = 0; it < PPC/PTS; ++it) {
        const int gp = blockIdx.x*PPC + it*PTS + pp;   // b*N + n
        const int b  = gp >> 13;

        if (t < 16) {
            int nb = idxg[gp*Kc + t];
            sIdxP[t] = nb;
            const float* pc = g_pt + (size_t)gp*3;
            const float* pn = g_pt + ((size_t)b*Nc + nb)*3;
            sRelP[t]      = pc[0] - pn[0];
            sRelP[16+t]   = pc[1] - pn[1];
            sRelP[32+t]   = pc[2] - pn[2];
        }
        BARP();

        // prefetch gathered features (4 neighbors x 4 channels) + residual
        float4 gx[4];
        #pragma unroll
        for (int l = 0; l < 4; l++) {
            int nb = sIdxP[jb*4 + l];
            gx[l] = *reinterpret_cast<const float4*>(
                xin + ((size_t)b*Nc + nb)*Cc + ob);
        }
        float resv = xin[(size_t)gp*Cc + t];

        unsigned long long acc[4][2];

        // ---- delta layer1: 64x3, relu ----
        init_bias(sm + FB1, ob, acc);
        #pragma unroll
        for (int c = 0; c < 3; c++) {
            ulonglong2 a = *reinterpret_cast<const ulonglong2*>(
                &sRelP[c*16 + jb*4]);
            float4 w = *reinterpret_cast<const float4*>(&sm[FW1 + c*64 + ob]);
            unsigned long long w0 = pk2(w.x), w1 = pk2(w.y),
                               w2 = pk2(w.z), w3 = pk2(w.w);
            acc[0][0] = ffma2(w0, a.x, acc[0][0]);
            acc[0][1] = ffma2(w0, a.y, acc[0][1]);
            acc[1][0] = ffma2(w1, a.x, acc[1][0]);
            acc[1][1] = ffma2(w1, a.y, acc[1][1]);
            acc[2][0] = ffma2(w2, a.x, acc[2][0]);
            acc[2][1] = ffma2(w2, a.y, acc[2][1]);
            acc[3][0] = ffma2(w3, a.x, acc[3][0]);
            acc[3][1] = ffma2(w3, a.y, acc[3][1]);
        }
        store_act(pA, jb, ob, acc, true);
        BARP();

        // ---- delta layer2: 64x64 + gathered x ----
        init_bias(sm + FB2, ob, acc);
        gemm64(sm + FW2, pA, jb, ob, acc);
        acc[0][0] = add2(acc[0][0], pk2p(gx[0].x, gx[1].x));
        acc[0][1] = add2(acc[0][1], pk2p(gx[2].x, gx[3].x));
        acc[1][0] = add2(acc[1][0], pk2p(gx[0].y, gx[1].y));
        acc[1][1] = add2(acc[1][1], pk2p(gx[2].y, gx[3].y));
        acc[2][0] = add2(acc[2][0], pk2p(gx[0].z, gx[1].z));
        acc[2][1] = add2(acc[2][1], pk2p(gx[2].z, gx[3].z));
        acc[3][0] = add2(acc[3][0], pk2p(gx[0].w, gx[1].w));
        acc[3][1] = add2(acc[3][1], pk2p(gx[2].w, gx[3].w));
        store_act(pB, jb, ob, acc, false);
        BARP();

        // ---- alpha layer1: 64x64, relu ----
        init_bias(sm + FB3, ob, acc);
        gemm64(sm + FWA1, pB, jb, ob, acc);
        store_act(pA, jb, ob, acc, true);
        BARP();

        // ---- alpha layer2: 64x64, relu folded into partial max over 4 j ----
        init_bias(sm + FB4, ob, acc);
        gemm64(sm + FWA2, pA, jb, ob, acc);
        {
            float m[4];
            #pragma unroll
            for (int k = 0; k < 4; k++) {
                float2 a = up2(acc[k][0]), c2 = up2(acc[k][1]);
                m[k] = fmaxf(fmaxf(fmaxf(a.x, a.y), fmaxf(c2.x, c2.y)), 0.f);
            }
            *reinterpret_cast<float4*>(&sPartP[jb*64 + ob]) =
                make_float4(m[0], m[1], m[2], m[3]);
        }
        BARP();

        // ---- final max over 4 partials; thread t owns channel o = t ----
        {
            float y = fmaxf(fmaxf(sPartP[t], sPartP[64 + t]),
                            fmaxf(sPartP[128 + t], sPartP[192 + t]));
            sYP[t] = y;
        }
        BARP();

        // ---- down: 64x64 + residual ----
        {
            float o = sm[FBD + t];
            #pragma unroll 16
            for (int c = 0; c < 64; c++)
                o = fmaf(sm[FWD + c*64 + t], sYP[c], o);
            xout[(size_t)gp*Cc + t] = o + resv;
        }
        BARP();
    }
}

// ---------------- launch ----------------
extern "C" void kernel_launch(void* const* d_in, const int* in_sizes, int n_in,
                              void* d_out, int out_size)
{
    const float* input_p = (const float*)d_in[0];
    const float* input_x = (const float*)d_in[1];
    const int*   idx     = (const int*)  d_in[2];
    const float* P[20];
    for (int i = 0; i < 20; i++) P[i] = (const float*)d_in[3 + i];
    float* out = (float*)d_out;

    cudaFuncSetAttribute(block_kernel,
        cudaFuncAttributeMaxDynamicSharedMemorySize, SMEM_BYTES);

    fold_kernel<<<2, 256>>>(P[0],P[1],P[2],P[3], P[4],P[5],P[6],P[7],
                            P[8],P[9],P[10],P[11], P[12],P[13],P[14],P[15],
                            P[16],P[17],P[18],P[19]);
    transpose_p_kernel<<<(Bc*Nc + 255)/256, 256>>>(input_p);
    {
        dim3 tb(32, 8), tg(Nc/32, Cc/32, Bc);
        transpose_in_kernel<<<tg, tb>>>(input_x);
    }
    block_kernel<<<(Bc*Nc)/PPC, 256, SMEM_BYTES>>>(idx, 0, 0); // xa -> xb
    block_kernel<<<(Bc*Nc)/PPC, 256, SMEM_BYTES>>>(idx, 1, 1); // xb -> xa
    {
        dim3 tb(32, 8), tg(Nc/32, Cc/32, Bc);
        transpose_out_kernel<<<tg, tb>>>(out + Bc*3*Nc);
    }
    cudaMemcpyAsync(out, input_p, (size_t)Bc*3*Nc*sizeof(float),
                    cudaMemcpyDeviceToDevice);
}

// round 7
// speedup vs baseline: 3.2664x; 1.1365x over previous
#include <cuda_runtime.h>
#include <cstdint>

typedef unsigned long long u64;

// Problem constants
#define Bc 4
#define Nc 8192
#define Cc 64
#define Kc 16
#define PPC 32            // points per CTA (sequential*inflight)
#define PTS 8             // points in flight (1 warp each)
#define BNS 0.99999500003749968f   // 1/sqrt(1+1e-5)

// folded-weight layout (floats) per block
#define FW1  0            // [3][64]  [c*64+o]
#define FW2  192          // [64][64] [c*64+o]
#define FWA1 (192+4096)
#define FWA2 (192+8192)
#define FWD  (192+12288)
#define FB1  (192+16384)
#define FB2  (FB1+64)
#define FB3  (FB1+128)
#define FB4  (FB1+192)
#define FBD  (FB1+256)
#define FOLD_SZ (FB1+320) // 16896 floats

// per-point smem region (floats): pA 1024 | pB 1024 | part 256 | y 64 | rel 48 | idx 16
#define PT_SZ   2432
#define PT_A    0
#define PT_B    1024
#define PT_PART 2048
#define PT_Y    2304
#define PT_REL  2368
#define PT_IDX  2416
#define SMEM_BYTES ((FOLD_SZ + PTS*PT_SZ) * 4)   // 145408 B

// ---------------- device scratch ----------------
__device__ __align__(16) float g_pt[Bc*Nc*3];
__device__ __align__(16) float g_xa[Bc*Nc*Cc];
__device__ __align__(16) float g_xb[Bc*Nc*Cc];
__device__ __align__(16) float g_fold[2*FOLD_SZ];

// ---------------- packed f32x2 helpers ----------------
__device__ __forceinline__ u64 ffma2(u64 a, u64 b, u64 c) {
    u64 d;
    asm("fma.rn.f32x2 %0, %1, %2, %3;" : "=l"(d) : "l"(a), "l"(b), "l"(c));
    return d;
}
__device__ __forceinline__ u64 add2(u64 a, u64 b) {
    u64 d;
    asm("add.rn.f32x2 %0, %1, %2;" : "=l"(d) : "l"(a), "l"(b));
    return d;
}
__device__ __forceinline__ u64 pk2(float x) {
    u64 r;
    asm("mov.b64 %0, {%1, %1};" : "=l"(r) : "f"(x));
    return r;
}
__device__ __forceinline__ u64 pk2p(float x, float y) {
    u64 r;
    asm("mov.b64 %0, {%1, %2};" : "=l"(r) : "f"(x), "f"(y));
    return r;
}
__device__ __forceinline__ float2 up2(u64 v) {
    float2 f;
    asm("mov.b64 {%0, %1}, %2;" : "=f"(f.x), "=f"(f.y) : "l"(v));
    return f;
}

// ---------------- fold BN into weights/biases ----------------
__global__ void fold_kernel(
    const float* __restrict__ dw1, const float* __restrict__ db1,
    const float* __restrict__ dg1, const float* __restrict__ dbe1,
    const float* __restrict__ dw2, const float* __restrict__ db2,
    const float* __restrict__ dg2, const float* __restrict__ dbe2,
    const float* __restrict__ aw1, const float* __restrict__ ab1,
    const float* __restrict__ ag1, const float* __restrict__ abe1,
    const float* __restrict__ aw2, const float* __restrict__ ab2,
    const float* __restrict__ ag2, const float* __restrict__ abe2,
    const float* __restrict__ lw,  const float* __restrict__ lb,
    const float* __restrict__ lg,  const float* __restrict__ lbe)
{
    const int blk = blockIdx.x;
    float* F = g_fold + blk*FOLD_SZ;
    const int tid = threadIdx.x;

    for (int t = tid; t < 192; t += 256) {
        int c = t >> 6, o = t & 63;
        F[FW1 + t] = dw1[blk*Cc*3 + o*3 + c] * dg1[blk*Cc + o] * BNS;
    }
    for (int t = tid; t < 4096; t += 256) {
        int c = t >> 6, o = t & 63;
        int g = o*64 + c;
        F[FW2  + t] = dw2[blk*4096 + g] * dg2[blk*Cc + o] * BNS;
        F[FWA1 + t] = aw1[blk*4096 + g] * ag1[blk*Cc + o] * BNS;
        F[FWA2 + t] = aw2[blk*4096 + g] * ag2[blk*Cc + o] * BNS;
        F[FWD  + t] = lw [blk*4096 + g] * lg [blk*Cc + o] * BNS;
    }
    for (int o = tid; o < 64; o += 256) {
        F[FB1+o] = db1[blk*Cc+o]*dg1[blk*Cc+o]*BNS + dbe1[blk*Cc+o];
        F[FB2+o] = db2[blk*Cc+o]*dg2[blk*Cc+o]*BNS + dbe2[blk*Cc+o];
        F[FB3+o] = ab1[blk*Cc+o]*ag1[blk*Cc+o]*BNS + abe1[blk*Cc+o];
        F[FB4+o] = ab2[blk*Cc+o]*ag2[blk*Cc+o]*BNS + abe2[blk*Cc+o];
        F[FBD+o] = lb [blk*Cc+o]*lg [blk*Cc+o]*BNS + lbe [blk*Cc+o];
    }
}

// ---------------- transposes ----------------
__global__ void transpose_p_kernel(const float* __restrict__ pin)
{
    int t = blockIdx.x*blockDim.x + threadIdx.x;
    if (t >= Bc*Nc) return;
    int b = t >> 13, n = t & (Nc-1);
    #pragma unroll
    for (int c = 0; c < 3; c++)
        g_pt[t*3 + c] = pin[((size_t)b*3 + c)*Nc + n];
}

__global__ void transpose_in_kernel(const float* __restrict__ src)
{
    __shared__ float tile[32][33];
    int b  = blockIdx.z;
    int n0 = blockIdx.x * 32;
    int c0 = blockIdx.y * 32;
    int tx = threadIdx.x, ty = threadIdx.y;
    #pragma unroll
    for (int i = 0; i < 32; i += 8)
        tile[ty+i][tx] = src[((size_t)b*Cc + c0+ty+i)*Nc + n0 + tx];
    __syncthreads();
    #pragma unroll
    for (int i = 0; i < 32; i += 8)
        g_xa[((size_t)b*Nc + n0+ty+i)*Cc + c0 + tx] = tile[tx][ty+i];
}

__global__ void transpose_out_kernel(float* __restrict__ dst)
{
    __shared__ float tile[32][33];
    int b  = blockIdx.z;
    int n0 = blockIdx.x * 32;
    int c0 = blockIdx.y * 32;
    int tx = threadIdx.x, ty = threadIdx.y;
    #pragma unroll
    for (int i = 0; i < 32; i += 8)
        tile[ty+i][tx] = g_xa[((size_t)b*Nc + n0+ty+i)*Cc + c0 + tx];
    __syncthreads();
    #pragma unroll
    for (int i = 0; i < 32; i += 8)
        dst[((size_t)b*Cc + c0+ty+i)*Nc + n0 + tx] = tile[tx][ty+i];
}

// ---------------- per-layer primitives (o-paired f32x2) ----------------
// acc[p][j]: p = output pair (channels ob+2p, ob+2p+1), j = local neighbor

__device__ __forceinline__ void init_bias_o(const float* __restrict__ Bv,
                                            int ob, u64 acc[4][4])
{
    ulonglong2 bA = *reinterpret_cast<const ulonglong2*>(&Bv[ob]);
    ulonglong2 bB = *reinterpret_cast<const ulonglong2*>(&Bv[ob + 4]);
    #pragma unroll
    for (int j = 0; j < 4; j++) {
        acc[0][j] = bA.x; acc[1][j] = bA.y;
        acc[2][j] = bB.x; acc[3][j] = bB.y;
    }
}

__device__ __forceinline__ void gemm_step(const float* __restrict__ Wc,
                                          float4 a4, int ob, u64 acc[4][4])
{
    ulonglong2 wA = *reinterpret_cast<const ulonglong2*>(&Wc[ob]);
    ulonglong2 wB = *reinterpret_cast<const ulonglong2*>(&Wc[ob + 4]);
    u64 a0 = pk2(a4.x), a1 = pk2(a4.y), a2 = pk2(a4.z), a3 = pk2(a4.w);
    acc[0][0] = ffma2(wA.x, a0, acc[0][0]);
    acc[0][1] = ffma2(wA.x, a1, acc[0][1]);
    acc[0][2] = ffma2(wA.x, a2, acc[0][2]);
    acc[0][3] = ffma2(wA.x, a3, acc[0][3]);
    acc[1][0] = ffma2(wA.y, a0, acc[1][0]);
    acc[1][1] = ffma2(wA.y, a1, acc[1][1]);
    acc[1][2] = ffma2(wA.y, a2, acc[1][2]);
    acc[1][3] = ffma2(wA.y, a3, acc[1][3]);
    acc[2][0] = ffma2(wB.x, a0, acc[2][0]);
    acc[2][1] = ffma2(wB.x, a1, acc[2][1]);
    acc[2][2] = ffma2(wB.x, a2, acc[2][2]);
    acc[2][3] = ffma2(wB.x, a3, acc[2][3]);
    acc[3][0] = ffma2(wB.y, a0, acc[3][0]);
    acc[3][1] = ffma2(wB.y, a1, acc[3][1]);
    acc[3][2] = ffma2(wB.y, a2, acc[3][2]);
    acc[3][3] = ffma2(wB.y, a3, acc[3][3]);
}

__device__ __forceinline__ void gemm64o(const float* __restrict__ W,
                                        const float* __restrict__ act,
                                        int ob, int jb, u64 acc[4][4])
{
    #pragma unroll 8
    for (int c = 0; c < 64; ++c) {
        float4 a4 = *reinterpret_cast<const float4*>(&act[c*16 + jb*4]);
        gemm_step(W + c*64, a4, ob, acc);
    }
}

__device__ __forceinline__ void store_act(float* __restrict__ dst,
                                          int ob, int jb, u64 acc[4][4],
                                          bool relu)
{
    #pragma unroll
    for (int p = 0; p < 4; p++) {
        float2 f0 = up2(acc[p][0]), f1 = up2(acc[p][1]),
               f2 = up2(acc[p][2]), f3 = up2(acc[p][3]);
        if (relu) {
            f0.x = fmaxf(f0.x, 0.f); f0.y = fmaxf(f0.y, 0.f);
            f1.x = fmaxf(f1.x, 0.f); f1.y = fmaxf(f1.y, 0.f);
            f2.x = fmaxf(f2.x, 0.f); f2.y = fmaxf(f2.y, 0.f);
            f3.x = fmaxf(f3.x, 0.f); f3.y = fmaxf(f3.y, 0.f);
        }
        *reinterpret_cast<ulonglong2*>(&dst[(ob + 2*p)*16 + jb*4]) =
            make_ulonglong2(pk2p(f0.x, f1.x), pk2p(f2.x, f3.x));
        *reinterpret_cast<ulonglong2*>(&dst[(ob + 2*p + 1)*16 + jb*4]) =
            make_ulonglong2(pk2p(f0.y, f1.y), pk2p(f2.y, f3.y));
    }
}

// ---------------- fused block kernel: 1 warp per point ----------------
__global__ void __launch_bounds__(256, 1)
block_kernel(const int* __restrict__ idxg, int blk, int dir)
{
    const float* __restrict__ xin  = dir ? g_xb : g_xa;
    float*       __restrict__ xout = dir ? g_xa : g_xb;

    extern __shared__ float sm[];
    const int tid = threadIdx.x;

    {   // load folded weights coalesced (float4)
        const float4* F4 = reinterpret_cast<const float4*>(g_fold + blk*FOLD_SZ);
        float4* S4 = reinterpret_cast<float4*>(sm);
        for (int t = tid; t < FOLD_SZ/4; t += 256) S4[t] = F4[t];
    }
    __syncthreads();

    const int pp = tid >> 5;          // warp = point slot 0..7
    const int l  = tid & 31;          // lane
    const int jb = l & 3;             // j-group (4 neighbors)
    const int og = l >> 2;            // 0..7
    const int ob = og * 8;            // 8 output channels (4 pairs)

    float* pA    = sm + FOLD_SZ + pp*PT_SZ + PT_A;
    float* pB    = sm + FOLD_SZ + pp*PT_SZ + PT_B;
    float* sPart = sm + FOLD_SZ + pp*PT_SZ + PT_PART;
    float* sY    = sm + FOLD_SZ + pp*PT_SZ + PT_Y;
    float* sRel  = sm + FOLD_SZ + pp*PT_SZ + PT_REL;
    int*   sIdx  = (int*)(sm + FOLD_SZ + pp*PT_SZ + PT_IDX);

    for (int it = 0; it < PPC/PTS; ++it) {
        const int gp = blockIdx.x*PPC + it*PTS + pp;   // b*N + n
        const int b  = gp >> 13;

        if (l < 16) sIdx[l] = idxg[gp*Kc + l];
        __syncwarp();

        // prefetch gathered x (8 LDG.128) + residual (consumed much later)
        ulonglong2 gA[4], gB[4];
        #pragma unroll
        for (int jj = 0; jj < 4; jj++) {
            int nb = sIdx[jb*4 + jj];
            const float* row = xin + ((size_t)b*Nc + nb)*Cc;
            gA[jj] = *reinterpret_cast<const ulonglong2*>(row + ob);
            gB[jj] = *reinterpret_cast<const ulonglong2*>(row + ob + 4);
        }
        float2 res = *reinterpret_cast<const float2*>(&xin[(size_t)gp*Cc + 2*l]);

        if (l < 16) {
            int nb = sIdx[l];
            const float* pc = g_pt + (size_t)gp*3;
            const float* pn = g_pt + ((size_t)b*Nc + nb)*3;
            sRel[l]      = pc[0] - pn[0];
            sRel[16+l]   = pc[1] - pn[1];
            sRel[32+l]   = pc[2] - pn[2];
        }
        __syncwarp();

        u64 acc[4][4];

        // ---- delta layer1: 64x3, relu ----
        init_bias_o(sm + FB1, ob, acc);
        #pragma unroll
        for (int c = 0; c < 3; c++) {
            float4 a4 = *reinterpret_cast<const float4*>(&sRel[c*16 + jb*4]);
            gemm_step(sm + FW1 + c*64, a4, ob, acc);
        }
        store_act(pA, ob, jb, acc, true);
        __syncwarp();

        // ---- delta layer2: 64x64 + gathered x (no relu) ----
        init_bias_o(sm + FB2, ob, acc);
        gemm64o(sm + FW2, pA, ob, jb, acc);
        #pragma unroll
        for (int jj = 0; jj < 4; jj++) {
            acc[0][jj] = add2(acc[0][jj], gA[jj].x);
            acc[1][jj] = add2(acc[1][jj], gA[jj].y);
            acc[2][jj] = add2(acc[2][jj], gB[jj].x);
            acc[3][jj] = add2(acc[3][jj], gB[jj].y);
        }
        store_act(pB, ob, jb, acc, false);
        __syncwarp();

        // ---- alpha layer1: 64x64, relu ----
        init_bias_o(sm + FB3, ob, acc);
        gemm64o(sm + FWA1, pB, ob, jb, acc);
        store_act(pA, ob, jb, acc, true);
        __syncwarp();

        // ---- alpha layer2: 64x64; relu folded into partial max over 4 j ----
        init_bias_o(sm + FB4, ob, acc);
        gemm64o(sm + FWA2, pA, ob, jb, acc);
        #pragma unroll
        for (int p = 0; p < 4; p++) {
            float2 f0 = up2(acc[p][0]), f1 = up2(acc[p][1]),
                   f2 = up2(acc[p][2]), f3 = up2(acc[p][3]);
            float mlo = fmaxf(fmaxf(f0.x, f1.x), fmaxf(f2.x, f3.x));
            float mhi = fmaxf(fmaxf(f0.y, f1.y), fmaxf(f2.y, f3.y));
            mlo = fmaxf(mlo, 0.f); mhi = fmaxf(mhi, 0.f);
            *reinterpret_cast<u64*>(&sPart[jb*64 + ob + 2*p]) = pk2p(mlo, mhi);
        }
        __syncwarp();

        // ---- final max over 4 j-groups; lane l owns channels 2l, 2l+1 ----
        {
            float2 y0 = *reinterpret_cast<const float2*>(&sPart[2*l]);
            float2 y1 = *reinterpret_cast<const float2*>(&sPart[64 + 2*l]);
            float2 y2 = *reinterpret_cast<const float2*>(&sPart[128 + 2*l]);
            float2 y3 = *reinterpret_cast<const float2*>(&sPart[192 + 2*l]);
            float2 y;
            y.x = fmaxf(fmaxf(y0.x, y1.x), fmaxf(y2.x, y3.x));
            y.y = fmaxf(fmaxf(y0.y, y1.y), fmaxf(y2.y, y3.y));
            *reinterpret_cast<float2*>(&sY[2*l]) = y;
        }
        __syncwarp();

        // ---- down: 64x64 + residual ----
        {
            u64 accd = *reinterpret_cast<const u64*>(&sm[FBD + 2*l]);
            #pragma unroll 16
            for (int c = 0; c < 64; c++) {
                u64 w = *reinterpret_cast<const u64*>(&sm[FWD + c*64 + 2*l]);
                accd = ffma2(w, pk2(sY[c]), accd);
            }
            float2 fd = up2(accd);
            float2 o2 = make_float2(fd.x + res.x, fd.y + res.y);
            *reinterpret_cast<float2*>(&xout[(size_t)gp*Cc + 2*l]) = o2;
        }
        __syncwarp();
    }
}

// ---------------- launch ----------------
extern "C" void kernel_launch(void* const* d_in, const int* in_sizes, int n_in,
                              void* d_out, int out_size)
{
    const float* input_p = (const float*)d_in[0];
    const float* input_x = (const float*)d_in[1];
    const int*   idx     = (const int*)  d_in[2];
    const float* P[20];
    for (int i = 0; i < 20; i++) P[i] = (const float*)d_in[3 + i];
    float* out = (float*)d_out;

    cudaFuncSetAttribute(block_kernel,
        cudaFuncAttributeMaxDynamicSharedMemorySize, SMEM_BYTES);

    fold_kernel<<<2, 256>>>(P[0],P[1],P[2],P[3], P[4],P[5],P[6],P[7],
                            P[8],P[9],P[10],P[11], P[12],P[13],P[14],P[15],
                            P[16],P[17],P[18],P[19]);
    transpose_p_kernel<<<(Bc*Nc + 255)/256, 256>>>(input_p);
    {
        dim3 tb(32, 8), tg(Nc/32, Cc/32, Bc);
        transpose_in_kernel<<<tg, tb>>>(input_x);
    }
    block_kernel<<<(Bc*Nc)/PPC, 256, SMEM_BYTES>>>(idx, 0, 0); // xa -> xb
    block_kernel<<<(Bc*Nc)/PPC, 256, SMEM_BYTES>>>(idx, 1, 1); // xb -> xa
    {
        dim3 tb(32, 8), tg(Nc/32, Cc/32, Bc);
        transpose_out_kernel<<<tg, tb>>>(out + Bc*3*Nc);
    }
    cudaMemcpyAsync(out, input_p, (size_t)Bc*3*Nc*sizeof(float),
                    cudaMemcpyDeviceToDevice);
}

// round 8
// speedup vs baseline: 3.4625x; 1.0600x over previous
#include <cuda_runtime.h>
#include <cstdint>

typedef unsigned long long u64;

// Problem constants
#define Bc 4
#define Nc 8192
#define Cc 64
#define Kc 16
#define PPC 24            // points per CTA (2 iterations x 12 slots)
#define PTS 12            // points in flight (1 warp each)
#define NTHR (PTS*32)
#define BNS 0.99999500003749968f   // 1/sqrt(1+1e-5)

// folded-weight layout (floats) per block
#define FW1  0            // [3][64]  [c*64+o]
#define FW2  192          // [64][64] [c*64+o]
#define FWA1 (192+4096)
#define FWA2 (192+8192)
#define FWD  (192+12288)
#define FB1  (192+16384)
#define FB2  (FB1+64)
#define FB3  (FB1+128)
#define FB4  (FB1+192)
#define FBD  (FB1+256)
#define FOLD_SZ (FB1+320) // 16896 floats

// per-point smem region (floats)
#define PT_SZ   2432
#define PT_A    0
#define PT_B    1024
#define PT_PART 2048
#define PT_Y    2304
#define PT_REL  2368
#define PT_IDX  2416
#define SMEM_BYTES ((FOLD_SZ + PTS*PT_SZ) * 4)   // 184320 B

// ---------------- device scratch ----------------
__device__ __align__(16) float g_pt[Bc*Nc*3];
__device__ __align__(16) float g_xa[Bc*Nc*Cc];
__device__ __align__(16) float g_xb[Bc*Nc*Cc];
__device__ __align__(16) float g_fold[2*FOLD_SZ];

// ---------------- packed f32x2 helpers ----------------
__device__ __forceinline__ u64 ffma2(u64 a, u64 b, u64 c) {
    u64 d;
    asm("fma.rn.f32x2 %0, %1, %2, %3;" : "=l"(d) : "l"(a), "l"(b), "l"(c));
    return d;
}
__device__ __forceinline__ u64 add2(u64 a, u64 b) {
    u64 d;
    asm("add.rn.f32x2 %0, %1, %2;" : "=l"(d) : "l"(a), "l"(b));
    return d;
}
__device__ __forceinline__ u64 pk2(float x) {
    u64 r;
    asm("mov.b64 %0, {%1, %1};" : "=l"(r) : "f"(x));
    return r;
}
__device__ __forceinline__ u64 pk2p(float x, float y) {
    u64 r;
    asm("mov.b64 %0, {%1, %2};" : "=l"(r) : "f"(x), "f"(y));
    return r;
}
__device__ __forceinline__ float2 up2(u64 v) {
    float2 f;
    asm("mov.b64 {%0, %1}, %2;" : "=f"(f.x), "=f"(f.y) : "l"(v));
    return f;
}

// ---------------- fold BN into weights/biases ----------------
__global__ void fold_kernel(
    const float* __restrict__ dw1, const float* __restrict__ db1,
    const float* __restrict__ dg1, const float* __restrict__ dbe1,
    const float* __restrict__ dw2, const float* __restrict__ db2,
    const float* __restrict__ dg2, const float* __restrict__ dbe2,
    const float* __restrict__ aw1, const float* __restrict__ ab1,
    const float* __restrict__ ag1, const float* __restrict__ abe1,
    const float* __restrict__ aw2, const float* __restrict__ ab2,
    const float* __restrict__ ag2, const float* __restrict__ abe2,
    const float* __restrict__ lw,  const float* __restrict__ lb,
    const float* __restrict__ lg,  const float* __restrict__ lbe)
{
    const int blk = blockIdx.x;
    float* F = g_fold + blk*FOLD_SZ;
    const int tid = threadIdx.x;

    for (int t = tid; t < 192; t += 256) {
        int c = t >> 6, o = t & 63;
        F[FW1 + t] = dw1[blk*Cc*3 + o*3 + c] * dg1[blk*Cc + o] * BNS;
    }
    for (int t = tid; t < 4096; t += 256) {
        int c = t >> 6, o = t & 63;
        int g = o*64 + c;
        F[FW2  + t] = dw2[blk*4096 + g] * dg2[blk*Cc + o] * BNS;
        F[FWA1 + t] = aw1[blk*4096 + g] * ag1[blk*Cc + o] * BNS;
        F[FWA2 + t] = aw2[blk*4096 + g] * ag2[blk*Cc + o] * BNS;
        F[FWD  + t] = lw [blk*4096 + g] * lg [blk*Cc + o] * BNS;
    }
    for (int o = tid; o < 64; o += 256) {
        F[FB1+o] = db1[blk*Cc+o]*dg1[blk*Cc+o]*BNS + dbe1[blk*Cc+o];
        F[FB2+o] = db2[blk*Cc+o]*dg2[blk*Cc+o]*BNS + dbe2[blk*Cc+o];
        F[FB3+o] = ab1[blk*Cc+o]*ag1[blk*Cc+o]*BNS + abe1[blk*Cc+o];
        F[FB4+o] = ab2[blk*Cc+o]*ag2[blk*Cc+o]*BNS + abe2[blk*Cc+o];
        F[FBD+o] = lb [blk*Cc+o]*lg [blk*Cc+o]*BNS + lbe [blk*Cc+o];
    }
}

// ---------------- transposes ----------------
__global__ void transpose_p_kernel(const float* __restrict__ pin)
{
    int t = blockIdx.x*blockDim.x + threadIdx.x;
    if (t >= Bc*Nc) return;
    int b = t >> 13, n = t & (Nc-1);
    #pragma unroll
    for (int c = 0; c < 3; c++)
        g_pt[t*3 + c] = pin[((size_t)b*3 + c)*Nc + n];
}

__global__ void transpose_in_kernel(const float* __restrict__ src)
{
    __shared__ float tile[32][33];
    int b  = blockIdx.z;
    int n0 = blockIdx.x * 32;
    int c0 = blockIdx.y * 32;
    int tx = threadIdx.x, ty = threadIdx.y;
    #pragma unroll
    for (int i = 0; i < 32; i += 8)
        tile[ty+i][tx] = src[((size_t)b*Cc + c0+ty+i)*Nc + n0 + tx];
    __syncthreads();
    #pragma unroll
    for (int i = 0; i < 32; i += 8)
        g_xa[((size_t)b*Nc + n0+ty+i)*Cc + c0 + tx] = tile[tx][ty+i];
}

__global__ void transpose_out_kernel(float* __restrict__ dst)
{
    __shared__ float tile[32][33];
    int b  = blockIdx.z;
    int n0 = blockIdx.x * 32;
    int c0 = blockIdx.y * 32;
    int tx = threadIdx.x, ty = threadIdx.y;
    #pragma unroll
    for (int i = 0; i < 32; i += 8)
        tile[ty+i][tx] = g_xa[((size_t)b*Nc + n0+ty+i)*Cc + c0 + tx];
    __syncthreads();
    #pragma unroll
    for (int i = 0; i < 32; i += 8)
        dst[((size_t)b*Cc + c0+ty+i)*Nc + n0 + tx] = tile[tx][ty+i];
}

// ---------------- per-layer primitives (o-paired f32x2) ----------------
__device__ __forceinline__ void init_bias_o(const float* __restrict__ Bv,
                                            int ob, u64 acc[4][4])
{
    ulonglong2 bA = *reinterpret_cast<const ulonglong2*>(&Bv[ob]);
    ulonglong2 bB = *reinterpret_cast<const ulonglong2*>(&Bv[ob + 4]);
    #pragma unroll
    for (int j = 0; j < 4; j++) {
        acc[0][j] = bA.x; acc[1][j] = bA.y;
        acc[2][j] = bB.x; acc[3][j] = bB.y;
    }
}

__device__ __forceinline__ void gemm_step(const float* __restrict__ Wc,
                                          float4 a4, int ob, u64 acc[4][4])
{
    ulonglong2 wA = *reinterpret_cast<const ulonglong2*>(&Wc[ob]);
    ulonglong2 wB = *reinterpret_cast<const ulonglong2*>(&Wc[ob + 4]);
    u64 a0 = pk2(a4.x), a1 = pk2(a4.y), a2 = pk2(a4.z), a3 = pk2(a4.w);
    acc[0][0] = ffma2(wA.x, a0, acc[0][0]);
    acc[0][1] = ffma2(wA.x, a1, acc[0][1]);
    acc[0][2] = ffma2(wA.x, a2, acc[0][2]);
    acc[0][3] = ffma2(wA.x, a3, acc[0][3]);
    acc[1][0] = ffma2(wA.y, a0, acc[1][0]);
    acc[1][1] = ffma2(wA.y, a1, acc[1][1]);
    acc[1][2] = ffma2(wA.y, a2, acc[1][2]);
    acc[1][3] = ffma2(wA.y, a3, acc[1][3]);
    acc[2][0] = ffma2(wB.x, a0, acc[2][0]);
    acc[2][1] = ffma2(wB.x, a1, acc[2][1]);
    acc[2][2] = ffma2(wB.x, a2, acc[2][2]);
    acc[2][3] = ffma2(wB.x, a3, acc[2][3]);
    acc[3][0] = ffma2(wB.y, a0, acc[3][0]);
    acc[3][1] = ffma2(wB.y, a1, acc[3][1]);
    acc[3][2] = ffma2(wB.y, a2, acc[3][2]);
    acc[3][3] = ffma2(wB.y, a3, acc[3][3]);
}

__device__ __forceinline__ void gemm64o(const float* __restrict__ W,
                                        const float* __restrict__ act,
                                        int ob, int jb, u64 acc[4][4])
{
    #pragma unroll 8
    for (int c = 0; c < 64; ++c) {
        float4 a4 = *reinterpret_cast<const float4*>(&act[c*16 + jb*4]);
        gemm_step(W + c*64, a4, ob, acc);
    }
}

__device__ __forceinline__ void store_act(float* __restrict__ dst,
                                          int ob, int jb, u64 acc[4][4],
                                          bool relu)
{
    #pragma unroll
    for (int p = 0; p < 4; p++) {
        float2 f0 = up2(acc[p][0]), f1 = up2(acc[p][1]),
               f2 = up2(acc[p][2]), f3 = up2(acc[p][3]);
        if (relu) {
            f0.x = fmaxf(f0.x, 0.f); f0.y = fmaxf(f0.y, 0.f);
            f1.x = fmaxf(f1.x, 0.f); f1.y = fmaxf(f1.y, 0.f);
            f2.x = fmaxf(f2.x, 0.f); f2.y = fmaxf(f2.y, 0.f);
            f3.x = fmaxf(f3.x, 0.f); f3.y = fmaxf(f3.y, 0.f);
        }
        *reinterpret_cast<ulonglong2*>(&dst[(ob + 2*p)*16 + jb*4]) =
            make_ulonglong2(pk2p(f0.x, f1.x), pk2p(f2.x, f3.x));
        *reinterpret_cast<ulonglong2*>(&dst[(ob + 2*p + 1)*16 + jb*4]) =
            make_ulonglong2(pk2p(f0.y, f1.y), pk2p(f2.y, f3.y));
    }
}

// ---------------- fused block kernel: 1 warp per point ----------------
__global__ void __launch_bounds__(NTHR, 1)
block_kernel(const int* __restrict__ idxg, int blk, int dir)
{
    const float* __restrict__ xin  = dir ? g_xb : g_xa;
    float*       __restrict__ xout = dir ? g_xa : g_xb;

    extern __shared__ float sm[];
    const int tid = threadIdx.x;

    {   // load folded weights coalesced (float4)
        const float4* F4 = reinterpret_cast<const float4*>(g_fold + blk*FOLD_SZ);
        float4* S4 = reinterpret_cast<float4*>(sm);
        for (int t = tid; t < FOLD_SZ/4; t += NTHR) S4[t] = F4[t];
    }
    __syncthreads();

    const int pp = tid >> 5;          // warp = point slot 0..PTS-1
    const int l  = tid & 31;          // lane
    const int jb = l & 3;             // j-group (4 neighbors)
    const int og = l >> 2;            // 0..7
    const int ob = og * 8;            // 8 output channels (4 pairs)

    float* pA    = sm + FOLD_SZ + pp*PT_SZ + PT_A;
    float* pB    = sm + FOLD_SZ + pp*PT_SZ + PT_B;
    float* sPart = sm + FOLD_SZ + pp*PT_SZ + PT_PART;
    float* sY    = sm + FOLD_SZ + pp*PT_SZ + PT_Y;
    float* sRel  = sm + FOLD_SZ + pp*PT_SZ + PT_REL;
    int*   sIdx  = (int*)(sm + FOLD_SZ + pp*PT_SZ + PT_IDX);

    #pragma unroll 1
    for (int it = 0; it < PPC/PTS; ++it) {
        const int gp = blockIdx.x*PPC + it*PTS + pp;   // b*N + n
        if (gp >= Bc*Nc) break;
        const int b  = gp >> 13;

        if (l < 16) sIdx[l] = idxg[gp*Kc + l];
        __syncwarp();

        // prefetch gathered x (8 LDG.128) + residual (consumed much later)
        ulonglong2 gA[4], gB[4];
        #pragma unroll
        for (int jj = 0; jj < 4; jj++) {
            int nb = sIdx[jb*4 + jj];
            const float* row = xin + ((size_t)b*Nc + nb)*Cc;
            gA[jj] = *reinterpret_cast<const ulonglong2*>(row + ob);
            gB[jj] = *reinterpret_cast<const ulonglong2*>(row + ob + 4);
        }
        float2 res = *reinterpret_cast<const float2*>(&xin[(size_t)gp*Cc + 2*l]);

        if (l < 16) {
            int nb = sIdx[l];
            const float* pc = g_pt + (size_t)gp*3;
            const float* pn = g_pt + ((size_t)b*Nc + nb)*3;
            sRel[l]      = pc[0] - pn[0];
            sRel[16+l]   = pc[1] - pn[1];
            sRel[32+l]   = pc[2] - pn[2];
        }
        __syncwarp();

        u64 acc[4][4];

        // ---- delta layer1: 64x3, relu ----
        init_bias_o(sm + FB1, ob, acc);
        #pragma unroll
        for (int c = 0; c < 3; c++) {
            float4 a4 = *reinterpret_cast<const float4*>(&sRel[c*16 + jb*4]);
            gemm_step(sm + FW1 + c*64, a4, ob, acc);
        }
        store_act(pA, ob, jb, acc, true);
        __syncwarp();

        // ---- delta layer2: 64x64 + gathered x (no relu) ----
        init_bias_o(sm + FB2, ob, acc);
        gemm64o(sm + FW2, pA, ob, jb, acc);
        #pragma unroll
        for (int jj = 0; jj < 4; jj++) {
            acc[0][jj] = add2(acc[0][jj], gA[jj].x);
            acc[1][jj] = add2(acc[1][jj], gA[jj].y);
            acc[2][jj] = add2(acc[2][jj], gB[jj].x);
            acc[3][jj] = add2(acc[3][jj], gB[jj].y);
        }
        store_act(pB, ob, jb, acc, false);
        __syncwarp();

        // ---- alpha layer1: 64x64, relu ----
        init_bias_o(sm + FB3, ob, acc);
        gemm64o(sm + FWA1, pB, ob, jb, acc);
        store_act(pA, ob, jb, acc, true);
        __syncwarp();

        // ---- alpha layer2: 64x64; relu folded into partial max over 4 j ----
        init_bias_o(sm + FB4, ob, acc);
        gemm64o(sm + FWA2, pA, ob, jb, acc);
        #pragma unroll
        for (int p = 0; p < 4; p++) {
            float2 f0 = up2(acc[p][0]), f1 = up2(acc[p][1]),
                   f2 = up2(acc[p][2]), f3 = up2(acc[p][3]);
            float mlo = fmaxf(fmaxf(f0.x, f1.x), fmaxf(f2.x, f3.x));
            float mhi = fmaxf(fmaxf(f0.y, f1.y), fmaxf(f2.y, f3.y));
            mlo = fmaxf(mlo, 0.f); mhi = fmaxf(mhi, 0.f);
            *reinterpret_cast<u64*>(&sPart[jb*64 + ob + 2*p]) = pk2p(mlo, mhi);
        }
        __syncwarp();

        // ---- final max over 4 j-groups; lane l owns channels 2l, 2l+1 ----
        {
            float2 y0 = *reinterpret_cast<const float2*>(&sPart[2*l]);
            float2 y1 = *reinterpret_cast<const float2*>(&sPart[64 + 2*l]);
            float2 y2 = *reinterpret_cast<const float2*>(&sPart[128 + 2*l]);
            float2 y3 = *reinterpret_cast<const float2*>(&sPart[192 + 2*l]);
            float2 y;
            y.x = fmaxf(fmaxf(y0.x, y1.x), fmaxf(y2.x, y3.x));
            y.y = fmaxf(fmaxf(y0.y, y1.y), fmaxf(y2.y, y3.y));
            *reinterpret_cast<float2*>(&sY[2*l]) = y;
        }
        __syncwarp();

        // ---- down: 64x64 + residual ----
        {
            u64 accd = *reinterpret_cast<const u64*>(&sm[FBD + 2*l]);
            #pragma unroll 16
            for (int c = 0; c < 64; c++) {
                u64 w = *reinterpret_cast<const u64*>(&sm[FWD + c*64 + 2*l]);
                accd = ffma2(w, pk2(sY[c]), accd);
            }
            float2 fd = up2(accd);
            float2 o2 = make_float2(fd.x + res.x, fd.y + res.y);
            *reinterpret_cast<float2*>(&xout[(size_t)gp*Cc + 2*l]) = o2;
        }
        __syncwarp();
    }
}

// ---------------- launch ----------------
extern "C" void kernel_launch(void* const* d_in, const int* in_sizes, int n_in,
                              void* d_out, int out_size)
{
    const float* input_p = (const float*)d_in[0];
    const float* input_x = (const float*)d_in[1];
    const int*   idx     = (const int*)  d_in[2];
    const float* P[20];
    for (int i = 0; i < 20; i++) P[i] = (const float*)d_in[3 + i];
    float* out = (float*)d_out;

    cudaFuncSetAttribute(block_kernel,
        cudaFuncAttributeMaxDynamicSharedMemorySize, SMEM_BYTES);

    fold_kernel<<<2, 256>>>(P[0],P[1],P[2],P[3], P[4],P[5],P[6],P[7],
                            P[8],P[9],P[10],P[11], P[12],P[13],P[14],P[15],
                            P[16],P[17],P[18],P[19]);
    transpose_p_kernel<<<(Bc*Nc + 255)/256, 256>>>(input_p);
    {
        dim3 tb(32, 8), tg(Nc/32, Cc/32, Bc);
        transpose_in_kernel<<<tg, tb>>>(input_x);
    }
    const int grid = (Bc*Nc + PPC - 1) / PPC;
    block_kernel<<<grid, NTHR, SMEM_BYTES>>>(idx, 0, 0); // xa -> xb
    block_kernel<<<grid, NTHR, SMEM_BYTES>>>(idx, 1, 1); // xb -> xa
    {
        dim3 tb(32, 8), tg(Nc/32, Cc/32, Bc);
        transpose_out_kernel<<<tg, tb>>>(out + Bc*3*Nc);
    }
    cudaMemcpyAsync(out, input_p, (size_t)Bc*3*Nc*sizeof(float),
                    cudaMemcpyDeviceToDevice);
}

// round 10
// speedup vs baseline: 9.2897x; 2.6829x over previous
#include <cuda_runtime.h>
#include <cuda_fp16.h>
#include <cstdint>

// Problem constants
#define Bc 4
#define Nc 8192
#define Cc 64
#define Kc 16
#define TPB_TILES 4           // tiles (of 8 points) per CTA
#define BNS 0.99999500003749968f

// smem byte offsets
#define SO_WP   0             // 3 layers x 8nt x 4s x 32lane x 8B = 24576
#define SO_WD   24576         // down weights fp32 [c][o] = 16384
#define SO_W1P  40960         // 64 x float4 (w1x,w1y,w1z,b1) = 1024
#define SO_BIAS 41984         // 256 floats: b2,b3,b4,bd = 1024
#define SO_Y    43008         // 8 x 68 floats = 2176
#define SO_REL  45184         // 4 warps x 32 x float4 = 2048
#define SO_IDX  47232         // 4 warps x 32 ints = 512
#define SMEM_TOTAL 47744

// ---------------- device scratch ----------------
__device__ __align__(16) float g_pt[Bc*Nc*3];
__device__ __align__(16) float g_xa[Bc*Nc*Cc];
__device__ __align__(16) float g_xb[Bc*Nc*Cc];
__device__ __align__(16) uint32_t g_wpk[2*6144];   // fragment-packed fp16 weights
__device__ __align__(16) float g_wdf[2*4096];      // down weights [c][o]
__device__ __align__(16) float g_w1p[2*256];       // 64 x (w1x,w1y,w1z,b1)
__device__ __align__(16) float g_bias[2*256];      // b2,b3,b4,bd

// ---------------- helpers ----------------
__device__ __forceinline__ uint32_t f16x2(float lo, float hi) {
    uint32_t r;
    asm("cvt.rn.f16x2.f32 %0, %1, %2;" : "=r"(r) : "f"(hi), "f"(lo));
    return r;
}
__device__ __forceinline__ void mma16816(float d[4], const uint32_t a[4],
                                         uint32_t b0, uint32_t b1) {
    asm volatile(
        "mma.sync.aligned.m16n8k16.row.col.f32.f16.f16.f32 "
        "{%0,%1,%2,%3}, {%4,%5,%6,%7}, {%8,%9}, {%0,%1,%2,%3};"
        : "+f"(d[0]), "+f"(d[1]), "+f"(d[2]), "+f"(d[3])
        : "r"(a[0]), "r"(a[1]), "r"(a[2]), "r"(a[3]), "r"(b0), "r"(b1));
}

// ---------------- fold: BN fold + fragment packing ----------------
__global__ void fold_kernel(
    const float* __restrict__ dw1, const float* __restrict__ db1,
    const float* __restrict__ dg1, const float* __restrict__ dbe1,
    const float* __restrict__ dw2, const float* __restrict__ db2,
    const float* __restrict__ dg2, const float* __restrict__ dbe2,
    const float* __restrict__ aw1, const float* __restrict__ ab1,
    const float* __restrict__ ag1, const float* __restrict__ abe1,
    const float* __restrict__ aw2, const float* __restrict__ ab2,
    const float* __restrict__ ag2, const float* __restrict__ abe2,
    const float* __restrict__ lw,  const float* __restrict__ lb,
    const float* __restrict__ lg,  const float* __restrict__ lbe)
{
    const int blk = blockIdx.x;
    const int tid = threadIdx.x;
    const float* wsrc[3] = {dw2, aw1, aw2};
    const float* gsrc[3] = {dg2, ag1, ag2};

    // fragment-packed fp16 weights: b0={W[k][n],W[k+1][n]}, b1={W[k+8][n],W[k+9][n]}
    for (int t = tid; t < 3072; t += 256) {
        int L = t >> 10, r = t & 1023;
        int nt = r >> 7, s = (r >> 5) & 3, lane = r & 31;
        int n = nt*8 + (lane >> 2);
        int k = s*16 + (lane & 3)*2;
        float gm = gsrc[L][blk*64 + n] * BNS;
        const float* W = wsrc[L] + blk*4096 + n*64;
        unsigned short h0 = __half_as_ushort(__float2half(W[k]   * gm));
        unsigned short h1 = __half_as_ushort(__float2half(W[k+1] * gm));
        unsigned short h8 = __half_as_ushort(__float2half(W[k+8] * gm));
        unsigned short h9 = __half_as_ushort(__float2half(W[k+9] * gm));
        g_wpk[blk*6144 + t*2 + 0] = (uint32_t)h0 | ((uint32_t)h1 << 16);
        g_wpk[blk*6144 + t*2 + 1] = (uint32_t)h8 | ((uint32_t)h9 << 16);
    }
    // down weights fp32 [c][o]
    for (int t = tid; t < 4096; t += 256) {
        int c = t >> 6, o = t & 63;
        g_wdf[blk*4096 + c*64 + o] = lw[blk*4096 + o*64 + c] * lg[blk*64 + o] * BNS;
    }
    // delta1 packed (w1x,w1y,w1z,b1fold)
    for (int ch = tid; ch < 64; ch += 256) {
        float gm = dg1[blk*64 + ch] * BNS;
        g_w1p[blk*256 + ch*4 + 0] = dw1[blk*192 + ch*3 + 0] * gm;
        g_w1p[blk*256 + ch*4 + 1] = dw1[blk*192 + ch*3 + 1] * gm;
        g_w1p[blk*256 + ch*4 + 2] = dw1[blk*192 + ch*3 + 2] * gm;
        g_w1p[blk*256 + ch*4 + 3] = db1[blk*64 + ch] * gm + dbe1[blk*64 + ch];
    }
    // biases b2,b3,b4,bd (BN-folded)
    for (int o = tid; o < 64; o += 256) {
        float* Bv = g_bias + blk*256;
        Bv[o]       = db2[blk*64+o]*dg2[blk*64+o]*BNS + dbe2[blk*64+o];
        Bv[64+o]    = ab1[blk*64+o]*ag1[blk*64+o]*BNS + abe1[blk*64+o];
        Bv[128+o]   = ab2[blk*64+o]*ag2[blk*64+o]*BNS + abe2[blk*64+o];
        Bv[192+o]   = lb[blk*64+o]*lg[blk*64+o]*BNS + lbe[blk*64+o];
    }
}

// ---------------- transposes ----------------
__global__ void transpose_p_kernel(const float* __restrict__ pin)
{
    int t = blockIdx.x*blockDim.x + threadIdx.x;
    if (t >= Bc*Nc) return;
    int b = t >> 13, n = t & (Nc-1);
    #pragma unroll
    for (int c = 0; c < 3; c++)
        g_pt[t*3 + c] = pin[((size_t)b*3 + c)*Nc + n];
}

__global__ void transpose_in_kernel(const float* __restrict__ src)
{
    __shared__ float tile[32][33];
    int b  = blockIdx.z;
    int n0 = blockIdx.x * 32;
    int c0 = blockIdx.y * 32;
    int tx = threadIdx.x, ty = threadIdx.y;
    #pragma unroll
    for (int i = 0; i < 32; i += 8)
        tile[ty+i][tx] = src[((size_t)b*Cc + c0+ty+i)*Nc + n0 + tx];
    __syncthreads();
    #pragma unroll
    for (int i = 0; i < 32; i += 8)
        g_xa[((size_t)b*Nc + n0+ty+i)*Cc + c0 + tx] = tile[tx][ty+i];
}

__global__ void transpose_out_kernel(float* __restrict__ dst)
{
    __shared__ float tile[32][33];
    int b  = blockIdx.z;
    int n0 = blockIdx.x * 32;
    int c0 = blockIdx.y * 32;
    int tx = threadIdx.x, ty = threadIdx.y;
    #pragma unroll
    for (int i = 0; i < 32; i += 8)
        tile[ty+i][tx] = g_xa[((size_t)b*Nc + n0+ty+i)*Cc + c0 + tx];
    __syncthreads();
    #pragma unroll
    for (int i = 0; i < 32; i += 8)
        dst[((size_t)b*Cc + c0+ty+i)*Nc + n0 + tx] = tile[tx][ty+i];
}

// ---------------- fused block kernel (warp MMA) ----------------
// 128 threads = 4 warps; each warp owns 2 points (2 m16 tiles) per tile iter.
__global__ void __launch_bounds__(128, 2)
block_kernel(const int* __restrict__ idxg, int blk, int dir)
{
    const float* __restrict__ xin  = dir ? g_xb : g_xa;
    float*       __restrict__ xout = dir ? g_xa : g_xb;

    extern __shared__ float sm[];
    char* smc = (char*)sm;
    const int tid  = threadIdx.x;
    const int warp = tid >> 5;
    const int lane = tid & 31;
    const int lq   = lane & 3;    // col quad
    const int lr   = lane >> 2;   // row group 0..7

    // cooperative copy-in
    {
        const uint4* s0 = (const uint4*)(g_wpk + blk*6144);
        uint4* d0 = (uint4*)(smc + SO_WP);
        for (int t = tid; t < 1536; t += 128) d0[t] = s0[t];
        const float4* s1 = (const float4*)(g_wdf + blk*4096);
        float4* d1 = (float4*)(smc + SO_WD);
        for (int t = tid; t < 1024; t += 128) d1[t] = s1[t];
        const float4* s2 = (const float4*)(g_w1p + blk*256);
        float4* d2 = (float4*)(smc + SO_W1P);
        for (int t = tid; t < 64; t += 128) d2[t] = s2[t];
        const float4* s3 = (const float4*)(g_bias + blk*256);
        float4* d3 = (float4*)(smc + SO_BIAS);
        for (int t = tid; t < 64; t += 128) d3[t] = s3[t];
    }
    __syncthreads();

    const char* smW1 = smc + SO_W1P;
    const float* biasp = (const float*)(smc + SO_BIAS);
    float* yw = (float*)(smc + SO_Y);
    float* relW = (float*)(smc + SO_REL) + warp*128;   // 32 x float4
    int*   idxW = (int*)(smc + SO_IDX) + warp*32;

    for (int tt = 0; tt < TPB_TILES; ++tt) {
        const int tilebase = (blockIdx.x*TPB_TILES + tt)*8;   // first point
        const int pbase = tilebase + warp*2;                  // warp's 2 points
        const int bb = pbase >> 13;

        // ---- stage idx + rel for warp's 32 (point,j) combos ----
        {
            int p0 = pbase + (lane >> 4);
            int nb = idxg[p0*Kc + (lane & 15)];
            idxW[lane] = nb;
            const float* pc = g_pt + (size_t)p0*3;
            const float* pn = g_pt + ((size_t)((p0 >> 13)*Nc + nb))*3;
            *(float4*)(relW + lane*4) =
                make_float4(pc[0]-pn[0], pc[1]-pn[1], pc[2]-pn[2], 0.f);
        }
        __syncwarp();

        // own rows: j = lr, j8 = lr+8 per mtile
        float4 relA[2], relB[2];
        int nbA[2], nbB[2];
        #pragma unroll
        for (int mt = 0; mt < 2; mt++) {
            relA[mt] = *(float4*)(relW + (mt*16 + lr)*4);
            relB[mt] = *(float4*)(relW + (mt*16 + 8 + lr)*4);
            nbA[mt] = idxW[mt*16 + lr];
            nbB[mt] = idxW[mt*16 + 8 + lr];
        }

        // ---- gx gather loads (issued early) ----
        float2 gxA[2][8], gxB[2][8];
        #pragma unroll
        for (int mt = 0; mt < 2; mt++) {
            const float* rA = xin + ((size_t)(bb*Nc + nbA[mt]))*Cc + 2*lq;
            const float* rB = xin + ((size_t)(bb*Nc + nbB[mt]))*Cc + 2*lq;
            #pragma unroll
            for (int nt = 0; nt < 8; nt++) {
                gxA[mt][nt] = *(const float2*)(rA + nt*8);
                gxB[mt][nt] = *(const float2*)(rB + nt*8);
            }
        }

        // ---- D1 (64x3 + relu) computed directly into A fragments ----
        uint32_t af[2][4][4];
        #pragma unroll
        for (int s = 0; s < 4; s++) {
            int ch0 = s*16 + 2*lq;
            float4 w0 = *(const float4*)(smW1 + (ch0+0)*16);
            float4 w1 = *(const float4*)(smW1 + (ch0+1)*16);
            float4 w8 = *(const float4*)(smW1 + (ch0+8)*16);
            float4 w9 = *(const float4*)(smW1 + (ch0+9)*16);
            #pragma unroll
            for (int mt = 0; mt < 2; mt++) {
                float4 ra = relA[mt], rb = relB[mt];
                float vj0 = fmaxf(fmaf(ra.z,w0.z,fmaf(ra.y,w0.y,fmaf(ra.x,w0.x,w0.w))), 0.f);
                float vj1 = fmaxf(fmaf(ra.z,w1.z,fmaf(ra.y,w1.y,fmaf(ra.x,w1.x,w1.w))), 0.f);
                float vj8 = fmaxf(fmaf(ra.z,w8.z,fmaf(ra.y,w8.y,fmaf(ra.x,w8.x,w8.w))), 0.f);
                float vj9 = fmaxf(fmaf(ra.z,w9.z,fmaf(ra.y,w9.y,fmaf(ra.x,w9.x,w9.w))), 0.f);
                float uj0 = fmaxf(fmaf(rb.z,w0.z,fmaf(rb.y,w0.y,fmaf(rb.x,w0.x,w0.w))), 0.f);
                float uj1 = fmaxf(fmaf(rb.z,w1.z,fmaf(rb.y,w1.y,fmaf(rb.x,w1.x,w1.w))), 0.f);
                float uj8 = fmaxf(fmaf(rb.z,w8.z,fmaf(rb.y,w8.y,fmaf(rb.x,w8.x,w8.w))), 0.f);
                float uj9 = fmaxf(fmaf(rb.z,w9.z,fmaf(rb.y,w9.y,fmaf(rb.x,w9.x,w9.w))), 0.f);
                af[mt][s][0] = f16x2(vj0, vj1);
                af[mt][s][1] = f16x2(uj0, uj1);
                af[mt][s][2] = f16x2(vj8, vj9);
                af[mt][s][3] = f16x2(uj8, uj9);
            }
        }

        float acc[2][8][4];

        // ================= 3 tensor-core layers =================
        #pragma unroll
        for (int L = 0; L < 3; L++) {
            const uint32_t* wpL = (const uint32_t*)(smc + SO_WP) + L*2048;
            #pragma unroll
            for (int mt = 0; mt < 2; mt++)
                #pragma unroll
                for (int nt = 0; nt < 8; nt++)
                    #pragma unroll
                    for (int e = 0; e < 4; e++) acc[mt][nt][e] = 0.f;

            #pragma unroll
            for (int s = 0; s < 4; s++) {
                #pragma unroll
                for (int nt = 0; nt < 8; nt++) {
                    uint2 bf = *(const uint2*)(wpL + ((nt*4 + s)*32 + lane)*2);
                    mma16816(acc[0][nt], af[0][s], bf.x, bf.y);
                    mma16816(acc[1][nt], af[1][s], bf.x, bf.y);
                }
            }

            if (L == 0) {
                // +b2 +gx, no relu -> next A fragments
                #pragma unroll
                for (int nt = 0; nt < 8; nt++) {
                    float2 bv = *(const float2*)(biasp + nt*8 + 2*lq);
                    #pragma unroll
                    for (int mt = 0; mt < 2; mt++) {
                        acc[mt][nt][0] += bv.x + gxA[mt][nt].x;
                        acc[mt][nt][1] += bv.y + gxA[mt][nt].y;
                        acc[mt][nt][2] += bv.x + gxB[mt][nt].x;
                        acc[mt][nt][3] += bv.y + gxB[mt][nt].y;
                    }
                }
                #pragma unroll
                for (int mt = 0; mt < 2; mt++)
                    #pragma unroll
                    for (int s = 0; s < 4; s++) {
                        af[mt][s][0] = f16x2(acc[mt][2*s][0],   acc[mt][2*s][1]);
                        af[mt][s][1] = f16x2(acc[mt][2*s][2],   acc[mt][2*s][3]);
                        af[mt][s][2] = f16x2(acc[mt][2*s+1][0], acc[mt][2*s+1][1]);
                        af[mt][s][3] = f16x2(acc[mt][2*s+1][2], acc[mt][2*s+1][3]);
                    }
            } else if (L == 1) {
                // +b3, relu -> next A fragments
                #pragma unroll
                for (int nt = 0; nt < 8; nt++) {
                    float2 bv = *(const float2*)(biasp + 64 + nt*8 + 2*lq);
                    #pragma unroll
                    for (int mt = 0; mt < 2; mt++) {
                        acc[mt][nt][0] = fmaxf(acc[mt][nt][0] + bv.x, 0.f);
                        acc[mt][nt][1] = fmaxf(acc[mt][nt][1] + bv.y, 0.f);
                        acc[mt][nt][2] = fmaxf(acc[mt][nt][2] + bv.x, 0.f);
                        acc[mt][nt][3] = fmaxf(acc[mt][nt][3] + bv.y, 0.f);
                    }
                }
                #pragma unroll
                for (int mt = 0; mt < 2; mt++)
                    #pragma unroll
                    for (int s = 0; s < 4; s++) {
                        af[mt][s][0] = f16x2(acc[mt][2*s][0],   acc[mt][2*s][1]);
                        af[mt][s][1] = f16x2(acc[mt][2*s][2],   acc[mt][2*s][3]);
                        af[mt][s][2] = f16x2(acc[mt][2*s+1][0], acc[mt][2*s+1][1]);
                        af[mt][s][3] = f16x2(acc[mt][2*s+1][2], acc[mt][2*s+1][3]);
                    }
            } else {
                // +b4, relu folded into max over 16 rows (= K neighbors)
                #pragma unroll
                for (int mt = 0; mt < 2; mt++) {
                    #pragma unroll
                    for (int nt = 0; nt < 8; nt++) {
                        float2 bv = *(const float2*)(biasp + 128 + nt*8 + 2*lq);
                        float m0 = fmaxf(fmaxf(acc[mt][nt][0], acc[mt][nt][2]) + bv.x, 0.f);
                        float m1 = fmaxf(fmaxf(acc[mt][nt][1], acc[mt][nt][3]) + bv.y, 0.f);
                        #pragma unroll
                        for (int o = 4; o < 32; o <<= 1) {
                            m0 = fmaxf(m0, __shfl_xor_sync(0xffffffffu, m0, o));
                            m1 = fmaxf(m1, __shfl_xor_sync(0xffffffffu, m1, o));
                        }
                        if (lane < 4)
                            *(float2*)(yw + (warp*2 + mt)*68 + nt*8 + 2*lane) =
                                make_float2(m0, m1);
                    }
                }
            }
        }
        __syncthreads();

        // ---- down: 64x64 fp32 + residual ----
        {
            const int pl = tid >> 4;
            const int o4 = (tid & 15) * 4;
            const int gp = tilebase + pl;
            float4 res4 = *(const float4*)(xin + (size_t)gp*Cc + o4);
            const float* yp  = yw + pl*68;
            const float* wdp = (const float*)(smc + SO_WD);
            float4 a = *(const float4*)(biasp + 192 + o4);
            #pragma unroll 16
            for (int c = 0; c < 64; c++) {
                float yv = yp[c];
                float4 w = *(const float4*)(wdp + c*64 + o4);
                a.x = fmaf(w.x, yv, a.x);
                a.y = fmaf(w.y, yv, a.y);
                a.z = fmaf(w.z, yv, a.z);
                a.w = fmaf(w.w, yv, a.w);
            }
            a.x += res4.x; a.y += res4.y; a.z += res4.z; a.w += res4.w;
            *(float4*)(xout + (size_t)gp*Cc + o4) = a;
        }
        __syncthreads();
    }
}

// ---------------- launch ----------------
extern "C" void kernel_launch(void* const* d_in, const int* in_sizes, int n_in,
                              void* d_out, int out_size)
{
    const float* input_p = (const float*)d_in[0];
    const float* input_x = (const float*)d_in[1];
    const int*   idx     = (const int*)  d_in[2];
    const float* P[20];
    for (int i = 0; i < 20; i++) P[i] = (const float*)d_in[3 + i];
    float* out = (float*)d_out;

    cudaFuncSetAttribute(block_kernel,
        cudaFuncAttributeMaxDynamicSharedMemorySize, SMEM_TOTAL);

    fold_kernel<<<2, 256>>>(P[0],P[1],P[2],P[3], P[4],P[5],P[6],P[7],
                            P[8],P[9],P[10],P[11], P[12],P[13],P[14],P[15],
                            P[16],P[17],P[18],P[19]);
    transpose_p_kernel<<<(Bc*Nc + 255)/256, 256>>>(input_p);
    {
        dim3 tb(32, 8), tg(Nc/32, Cc/32, Bc);
        transpose_in_kernel<<<tg, tb>>>(input_x);
    }
    const int grid = (Bc*Nc) / (8 * TPB_TILES);   // 1024
    block_kernel<<<grid, 128, SMEM_TOTAL>>>(idx, 0, 0);  // xa -> xb
    block_kernel<<<grid, 128, SMEM_TOTAL>>>(idx, 1, 1);  // xb -> xa
    {
        dim3 tb(32, 8), tg(Nc/32, Cc/32, Bc);
        transpose_out_kernel<<<tg, tb>>>(out + Bc*3*Nc);
    }
    cudaMemcpyAsync(out, input_p, (size_t)Bc*3*Nc*sizeof(float),
                    cudaMemcpyDeviceToDevice);
}

// round 11
// speedup vs baseline: 9.7789x; 1.0527x over previous
#include <cuda_runtime.h>
#include <cuda_fp16.h>
#include <cstdint>

// Problem constants
#define Bc 4
#define Nc 8192
#define Cc 64
#define Kc 16
#define TPB_TILES 4           // tiles (of 8 points) per CTA
#define BNS 0.99999500003749968f

// smem byte offsets
#define SO_WP   0             // 3 layers x 8nt x 4s x 32lane x 8B = 24576
#define SO_WD   24576         // down weights fp32 [c][o] = 16384
#define SO_W1P  40960         // 64 x float4 (w1x,w1y,w1z,b1) = 1024
#define SO_BIAS 41984         // 256 floats: b2,b3,b4,bd = 1024
#define SO_PW   43008         // per-warp: rel 512 | idx 128 | y 544 (stride 1280)
#define PW_STRIDE 1280
#define SMEM_TOTAL (SO_PW + 4*PW_STRIDE)   // 48128

// ---------------- device scratch ----------------
__device__ __align__(16) float g_pt[Bc*Nc*3];
__device__ __align__(16) float g_xa[Bc*Nc*Cc];
__device__ __align__(16) float g_xb[Bc*Nc*Cc];
__device__ __align__(16) uint32_t g_wpk[2*6144];   // fragment-packed fp16 weights
__device__ __align__(16) float g_wdf[2*4096];      // down weights [c][o]
__device__ __align__(16) float g_w1p[2*256];       // 64 x (w1x,w1y,w1z,b1)
__device__ __align__(16) float g_bias[2*256];      // b2,b3,b4,bd

// ---------------- helpers ----------------
__device__ __forceinline__ uint32_t f16x2(float lo, float hi) {
    uint32_t r;
    asm("cvt.rn.f16x2.f32 %0, %1, %2;" : "=r"(r) : "f"(hi), "f"(lo));
    return r;
}
__device__ __forceinline__ float2 uph2(uint32_t v) {
    __half2 h = *reinterpret_cast<__half2*>(&v);
    return __half22float2(h);
}
__device__ __forceinline__ void mma16816(float d[4], const uint32_t a[4],
                                         uint32_t b0, uint32_t b1) {
    asm volatile(
        "mma.sync.aligned.m16n8k16.row.col.f32.f16.f16.f32 "
        "{%0,%1,%2,%3}, {%4,%5,%6,%7}, {%8,%9}, {%0,%1,%2,%3};"
        : "+f"(d[0]), "+f"(d[1]), "+f"(d[2]), "+f"(d[3])
        : "r"(a[0]), "r"(a[1]), "r"(a[2]), "r"(a[3]), "r"(b0), "r"(b1));
}

// ---------------- fold: BN fold + fragment packing ----------------
__global__ void fold_kernel(
    const float* __restrict__ dw1, const float* __restrict__ db1,
    const float* __restrict__ dg1, const float* __restrict__ dbe1,
    const float* __restrict__ dw2, const float* __restrict__ db2,
    const float* __restrict__ dg2, const float* __restrict__ dbe2,
    const float* __restrict__ aw1, const float* __restrict__ ab1,
    const float* __restrict__ ag1, const float* __restrict__ abe1,
    const float* __restrict__ aw2, const float* __restrict__ ab2,
    const float* __restrict__ ag2, const float* __restrict__ abe2,
    const float* __restrict__ lw,  const float* __restrict__ lb,
    const float* __restrict__ lg,  const float* __restrict__ lbe)
{
    const int blk = blockIdx.x;
    const int tid = threadIdx.x;
    const float* wsrc[3] = {dw2, aw1, aw2};
    const float* gsrc[3] = {dg2, ag1, ag2};

    for (int t = tid; t < 3072; t += 256) {
        int L = t >> 10, r = t & 1023;
        int nt = r >> 7, s = (r >> 5) & 3, lane = r & 31;
        int n = nt*8 + (lane >> 2);
        int k = s*16 + (lane & 3)*2;
        float gm = gsrc[L][blk*64 + n] * BNS;
        const float* W = wsrc[L] + blk*4096 + n*64;
        unsigned short h0 = __half_as_ushort(__float2half(W[k]   * gm));
        unsigned short h1 = __half_as_ushort(__float2half(W[k+1] * gm));
        unsigned short h8 = __half_as_ushort(__float2half(W[k+8] * gm));
        unsigned short h9 = __half_as_ushort(__float2half(W[k+9] * gm));
        g_wpk[blk*6144 + t*2 + 0] = (uint32_t)h0 | ((uint32_t)h1 << 16);
        g_wpk[blk*6144 + t*2 + 1] = (uint32_t)h8 | ((uint32_t)h9 << 16);
    }
    for (int t = tid; t < 4096; t += 256) {
        int c = t >> 6, o = t & 63;
        g_wdf[blk*4096 + c*64 + o] = lw[blk*4096 + o*64 + c] * lg[blk*64 + o] * BNS;
    }
    for (int ch = tid; ch < 64; ch += 256) {
        float gm = dg1[blk*64 + ch] * BNS;
        g_w1p[blk*256 + ch*4 + 0] = dw1[blk*192 + ch*3 + 0] * gm;
        g_w1p[blk*256 + ch*4 + 1] = dw1[blk*192 + ch*3 + 1] * gm;
        g_w1p[blk*256 + ch*4 + 2] = dw1[blk*192 + ch*3 + 2] * gm;
        g_w1p[blk*256 + ch*4 + 3] = db1[blk*64 + ch] * gm + dbe1[blk*64 + ch];
    }
    for (int o = tid; o < 64; o += 256) {
        float* Bv = g_bias + blk*256;
        Bv[o]       = db2[blk*64+o]*dg2[blk*64+o]*BNS + dbe2[blk*64+o];
        Bv[64+o]    = ab1[blk*64+o]*ag1[blk*64+o]*BNS + abe1[blk*64+o];
        Bv[128+o]   = ab2[blk*64+o]*ag2[blk*64+o]*BNS + abe2[blk*64+o];
        Bv[192+o]   = lb[blk*64+o]*lg[blk*64+o]*BNS + lbe[blk*64+o];
    }
}

// ---------------- transposes ----------------
__global__ void transpose_p_kernel(const float* __restrict__ pin)
{
    int t = blockIdx.x*blockDim.x + threadIdx.x;
    if (t >= Bc*Nc) return;
    int b = t >> 13, n = t & (Nc-1);
    #pragma unroll
    for (int c = 0; c < 3; c++)
        g_pt[t*3 + c] = pin[((size_t)b*3 + c)*Nc + n];
}

__global__ void transpose_in_kernel(const float* __restrict__ src)
{
    __shared__ float tile[32][33];
    int b  = blockIdx.z;
    int n0 = blockIdx.x * 32;
    int c0 = blockIdx.y * 32;
    int tx = threadIdx.x, ty = threadIdx.y;
    #pragma unroll
    for (int i = 0; i < 32; i += 8)
        tile[ty+i][tx] = src[((size_t)b*Cc + c0+ty+i)*Nc + n0 + tx];
    __syncthreads();
    #pragma unroll
    for (int i = 0; i < 32; i += 8)
        g_xa[((size_t)b*Nc + n0+ty+i)*Cc + c0 + tx] = tile[tx][ty+i];
}

__global__ void transpose_out_kernel(float* __restrict__ dst)
{
    __shared__ float tile[32][33];
    int b  = blockIdx.z;
    int n0 = blockIdx.x * 32;
    int c0 = blockIdx.y * 32;
    int tx = threadIdx.x, ty = threadIdx.y;
    #pragma unroll
    for (int i = 0; i < 32; i += 8)
        tile[ty+i][tx] = g_xa[((size_t)b*Nc + n0+ty+i)*Cc + c0 + tx];
    __syncthreads();
    #pragma unroll
    for (int i = 0; i < 32; i += 8)
        dst[((size_t)b*Cc + c0+ty+i)*Nc + n0 + tx] = tile[tx][ty+i];
}

// ---------------- fused block kernel (warp MMA, warp-independent) ----------------
__global__ void __launch_bounds__(128, 3)
block_kernel(const int* __restrict__ idxg, int blk, int dir)
{
    const float* __restrict__ xin  = dir ? g_xb : g_xa;
    float*       __restrict__ xout = dir ? g_xa : g_xb;

    extern __shared__ float sm[];
    char* smc = (char*)sm;
    const int tid  = threadIdx.x;
    const int warp = tid >> 5;
    const int lane = tid & 31;
    const int lq   = lane & 3;    // col quad
    const int lr   = lane >> 2;   // row group 0..7

    // cooperative copy-in (only CTA-wide sync in the kernel)
    {
        const uint4* s0 = (const uint4*)(g_wpk + blk*6144);
        uint4* d0 = (uint4*)(smc + SO_WP);
        for (int t = tid; t < 1536; t += 128) d0[t] = s0[t];
        const float4* s1 = (const float4*)(g_wdf + blk*4096);
        float4* d1 = (float4*)(smc + SO_WD);
        for (int t = tid; t < 1024; t += 128) d1[t] = s1[t];
        const float4* s2 = (const float4*)(g_w1p + blk*256);
        float4* d2 = (float4*)(smc + SO_W1P);
        for (int t = tid; t < 64; t += 128) d2[t] = s2[t];
        const float4* s3 = (const float4*)(g_bias + blk*256);
        float4* d3 = (float4*)(smc + SO_BIAS);
        for (int t = tid; t < 64; t += 128) d3[t] = s3[t];
    }
    __syncthreads();

    const char* smW1 = smc + SO_W1P;
    const float* biasp = (const float*)(smc + SO_BIAS);
    char* pw = smc + SO_PW + warp*PW_STRIDE;
    float* relW = (float*)pw;              // 32 x float4
    int*   idxW = (int*)(pw + 512);        // 32 ints
    float* yW   = (float*)(pw + 640);      // 2 x 68 floats

    for (int tt = 0; tt < TPB_TILES; ++tt) {
        const int tilebase = (blockIdx.x*TPB_TILES + tt)*8;
        const int pbase = tilebase + warp*2;      // warp's 2 points
        const int bb = pbase >> 13;

        // ---- stage idx + rel ----
        {
            int p0 = pbase + (lane >> 4);
            int nb = idxg[p0*Kc + (lane & 15)];
            idxW[lane] = nb;
            const float* pc = g_pt + (size_t)p0*3;
            const float* pn = g_pt + ((size_t)((p0 >> 13)*Nc + nb))*3;
            *(float4*)(relW + lane*4) =
                make_float4(pc[0]-pn[0], pc[1]-pn[1], pc[2]-pn[2], 0.f);
        }
        __syncwarp();

        float4 relA[2], relB[2];
        int nbA[2], nbB[2];
        #pragma unroll
        for (int mt = 0; mt < 2; mt++) {
            relA[mt] = *(float4*)(relW + (mt*16 + lr)*4);
            relB[mt] = *(float4*)(relW + (mt*16 + 8 + lr)*4);
            nbA[mt] = idxW[mt*16 + lr];
            nbB[mt] = idxW[mt*16 + 8 + lr];
        }

        // ---- gx gather -> packed fp16 (32 regs) ----
        uint32_t gxAh[2][8], gxBh[2][8];
        #pragma unroll
        for (int mt = 0; mt < 2; mt++) {
            const float* rA = xin + ((size_t)(bb*Nc + nbA[mt]))*Cc + 2*lq;
            const float* rB = xin + ((size_t)(bb*Nc + nbB[mt]))*Cc + 2*lq;
            #pragma unroll
            for (int nt = 0; nt < 8; nt++) {
                float2 a = *(const float2*)(rA + nt*8);
                float2 b = *(const float2*)(rB + nt*8);
                gxAh[mt][nt] = f16x2(a.x, a.y);
                gxBh[mt][nt] = f16x2(b.x, b.y);
            }
        }

        // ---- D1 (64x3 + relu) -> A fragments ----
        uint32_t af[2][4][4];
        #pragma unroll
        for (int s = 0; s < 4; s++) {
            int ch0 = s*16 + 2*lq;
            float4 w0 = *(const float4*)(smW1 + (ch0+0)*16);
            float4 w1 = *(const float4*)(smW1 + (ch0+1)*16);
            float4 w8 = *(const float4*)(smW1 + (ch0+8)*16);
            float4 w9 = *(const float4*)(smW1 + (ch0+9)*16);
            #pragma unroll
            for (int mt = 0; mt < 2; mt++) {
                float4 ra = relA[mt], rb = relB[mt];
                float vj0 = fmaxf(fmaf(ra.z,w0.z,fmaf(ra.y,w0.y,fmaf(ra.x,w0.x,w0.w))), 0.f);
                float vj1 = fmaxf(fmaf(ra.z,w1.z,fmaf(ra.y,w1.y,fmaf(ra.x,w1.x,w1.w))), 0.f);
                float vj8 = fmaxf(fmaf(ra.z,w8.z,fmaf(ra.y,w8.y,fmaf(ra.x,w8.x,w8.w))), 0.f);
                float vj9 = fmaxf(fmaf(ra.z,w9.z,fmaf(ra.y,w9.y,fmaf(ra.x,w9.x,w9.w))), 0.f);
                float uj0 = fmaxf(fmaf(rb.z,w0.z,fmaf(rb.y,w0.y,fmaf(rb.x,w0.x,w0.w))), 0.f);
                float uj1 = fmaxf(fmaf(rb.z,w1.z,fmaf(rb.y,w1.y,fmaf(rb.x,w1.x,w1.w))), 0.f);
                float uj8 = fmaxf(fmaf(rb.z,w8.z,fmaf(rb.y,w8.y,fmaf(rb.x,w8.x,w8.w))), 0.f);
                float uj9 = fmaxf(fmaf(rb.z,w9.z,fmaf(rb.y,w9.y,fmaf(rb.x,w9.x,w9.w))), 0.f);
                af[mt][s][0] = f16x2(vj0, vj1);
                af[mt][s][1] = f16x2(uj0, uj1);
                af[mt][s][2] = f16x2(vj8, vj9);
                af[mt][s][3] = f16x2(uj8, uj9);
            }
        }

        // ================= 3 tensor-core layers (nt-pair outer) =================
        #pragma unroll
        for (int L = 0; L < 3; L++) {
            const uint32_t* wpL = (const uint32_t*)(smc + SO_WP) + L*2048;
            uint32_t afn[2][4][4];
            #pragma unroll
            for (int sp = 0; sp < 4; sp++) {
                float acc[2][2][4];
                #pragma unroll
                for (int mt = 0; mt < 2; mt++)
                    #pragma unroll
                    for (int j = 0; j < 2; j++)
                        #pragma unroll
                        for (int e = 0; e < 4; e++) acc[mt][j][e] = 0.f;

                #pragma unroll
                for (int s = 0; s < 4; s++) {
                    uint2 b0 = *(const uint2*)(wpL + (((2*sp  )*4 + s)*32 + lane)*2);
                    uint2 b1 = *(const uint2*)(wpL + (((2*sp+1)*4 + s)*32 + lane)*2);
                    mma16816(acc[0][0], af[0][s], b0.x, b0.y);
                    mma16816(acc[1][0], af[1][s], b0.x, b0.y);
                    mma16816(acc[0][1], af[0][s], b1.x, b1.y);
                    mma16816(acc[1][1], af[1][s], b1.x, b1.y);
                }

                if (L == 0) {
                    #pragma unroll
                    for (int mt = 0; mt < 2; mt++) {
                        #pragma unroll
                        for (int j = 0; j < 2; j++) {
                            int nt = 2*sp + j;
                            float2 bv = *(const float2*)(biasp + nt*8 + 2*lq);
                            float2 ga = uph2(gxAh[mt][nt]);
                            float2 gb = uph2(gxBh[mt][nt]);
                            acc[mt][j][0] += bv.x + ga.x;
                            acc[mt][j][1] += bv.y + ga.y;
                            acc[mt][j][2] += bv.x + gb.x;
                            acc[mt][j][3] += bv.y + gb.y;
                        }
                        afn[mt][sp][0] = f16x2(acc[mt][0][0], acc[mt][0][1]);
                        afn[mt][sp][1] = f16x2(acc[mt][0][2], acc[mt][0][3]);
                        afn[mt][sp][2] = f16x2(acc[mt][1][0], acc[mt][1][1]);
                        afn[mt][sp][3] = f16x2(acc[mt][1][2], acc[mt][1][3]);
                    }
                } else if (L == 1) {
                    #pragma unroll
                    for (int mt = 0; mt < 2; mt++) {
                        #pragma unroll
                        for (int j = 0; j < 2; j++) {
                            int nt = 2*sp + j;
                            float2 bv = *(const float2*)(biasp + 64 + nt*8 + 2*lq);
                            acc[mt][j][0] = fmaxf(acc[mt][j][0] + bv.x, 0.f);
                            acc[mt][j][1] = fmaxf(acc[mt][j][1] + bv.y, 0.f);
                            acc[mt][j][2] = fmaxf(acc[mt][j][2] + bv.x, 0.f);
                            acc[mt][j][3] = fmaxf(acc[mt][j][3] + bv.y, 0.f);
                        }
                        afn[mt][sp][0] = f16x2(acc[mt][0][0], acc[mt][0][1]);
                        afn[mt][sp][1] = f16x2(acc[mt][0][2], acc[mt][0][3]);
                        afn[mt][sp][2] = f16x2(acc[mt][1][0], acc[mt][1][1]);
                        afn[mt][sp][3] = f16x2(acc[mt][1][2], acc[mt][1][3]);
                    }
                } else {
                    // +b4, relu folded into max over 16 rows (K neighbors)
                    #pragma unroll
                    for (int mt = 0; mt < 2; mt++) {
                        #pragma unroll
                        for (int j = 0; j < 2; j++) {
                            int nt = 2*sp + j;
                            float2 bv = *(const float2*)(biasp + 128 + nt*8 + 2*lq);
                            float m0 = fmaxf(fmaxf(acc[mt][j][0], acc[mt][j][2]) + bv.x, 0.f);
                            float m1 = fmaxf(fmaxf(acc[mt][j][1], acc[mt][j][3]) + bv.y, 0.f);
                            #pragma unroll
                            for (int o = 4; o < 32; o <<= 1) {
                                m0 = fmaxf(m0, __shfl_xor_sync(0xffffffffu, m0, o));
                                m1 = fmaxf(m1, __shfl_xor_sync(0xffffffffu, m1, o));
                            }
                            if (lane < 4)
                                *(float2*)(yW + mt*68 + nt*8 + 2*lane) =
                                    make_float2(m0, m1);
                        }
                    }
                }
            }
            if (L < 2) {
                #pragma unroll
                for (int mt = 0; mt < 2; mt++)
                    #pragma unroll
                    for (int s = 0; s < 4; s++)
                        #pragma unroll
                        for (int e = 0; e < 4; e++)
                            af[mt][s][e] = afn[mt][s][e];
            }
        }
        __syncwarp();

        // ---- down: per-warp, 2 points x 64 ch / 32 lanes ----
        {
            const int pl = lane >> 4;              // point 0/1
            const int o4 = (lane & 15) * 4;
            const int gp = pbase + pl;
            float4 res4 = *(const float4*)(xin + (size_t)gp*Cc + o4);
            const float* yp  = yW + pl*68;
            const float* wdp = (const float*)(smc + SO_WD);
            float4 a = *(const float4*)(biasp + 192 + o4);
            #pragma unroll 16
            for (int c = 0; c < 64; c++) {
                float yv = yp[c];
                float4 w = *(const float4*)(wdp + c*64 + o4);
                a.x = fmaf(w.x, yv, a.x);
                a.y = fmaf(w.y, yv, a.y);
                a.z = fmaf(w.z, yv, a.z);
                a.w = fmaf(w.w, yv, a.w);
            }
            a.x += res4.x; a.y += res4.y; a.z += res4.z; a.w += res4.w;
            *(float4*)(xout + (size_t)gp*Cc + o4) = a;
        }
        __syncwarp();
    }
}

// ---------------- launch ----------------
extern "C" void kernel_launch(void* const* d_in, const int* in_sizes, int n_in,
                              void* d_out, int out_size)
{
    const float* input_p = (const float*)d_in[0];
    const float* input_x = (const float*)d_in[1];
    const int*   idx     = (const int*)  d_in[2];
    const float* P[20];
    for (int i = 0; i < 20; i++) P[i] = (const float*)d_in[3 + i];
    float* out = (float*)d_out;

    cudaFuncSetAttribute(block_kernel,
        cudaFuncAttributeMaxDynamicSharedMemorySize, SMEM_TOTAL);

    fold_kernel<<<2, 256>>>(P[0],P[1],P[2],P[3], P[4],P[5],P[6],P[7],
                            P[8],P[9],P[10],P[11], P[12],P[13],P[14],P[15],
                            P[16],P[17],P[18],P[19]);
    transpose_p_kernel<<<(Bc*Nc + 255)/256, 256>>>(input_p);
    {
        dim3 tb(32, 8), tg(Nc/32, Cc/32, Bc);
        transpose_in_kernel<<<tg, tb>>>(input_x);
    }
    const int grid = (Bc*Nc) / (8 * TPB_TILES);   // 1024
    block_kernel<<<grid, 128, SMEM_TOTAL>>>(idx, 0, 0);  // xa -> xb
    block_kernel<<<grid, 128, SMEM_TOTAL>>>(idx, 1, 1);  // xb -> xa
    {
        dim3 tb(32, 8), tg(Nc/32, Cc/32, Bc);
        transpose_out_kernel<<<tg, tb>>>(out + Bc*3*Nc);
    }
    cudaMemcpyAsync(out, input_p, (size_t)Bc*3*Nc*sizeof(float),
                    cudaMemcpyDeviceToDevice);
}

// round 14
// speedup vs baseline: 11.6420x; 1.1905x over previous
#include <cuda_runtime.h>
#include <cuda_fp16.h>
#include <cstdint>

// Problem constants
#define Bc 4
#define Nc 8192
#define Cc 64
#define Kc 16
#define TPB_TILES 4           // tiles (of 8 points) per CTA
#define BNS 0.99999500003749968f

// smem byte offsets
#define SO_WP   0             // 3 layers x 8nt x 4s x 32lane x 8B = 24576
#define SO_WDH  24576         // down weights fp16 [c][o] = 8192
#define SO_W1P  32768         // 64 x float4 (w1x,w1y,w1z,b1) = 1024
#define SO_BIAS 33792         // 256 floats: b2,b3,b4,bd = 1024
#define SO_PW   34816         // per-warp: rel 512 | idx 128 | y 544 (stride 1280)
#define PW_STRIDE 1280
#define SMEM_TOTAL (SO_PW + 4*PW_STRIDE)   // 39936

// ---------------- device scratch ----------------
__device__ __align__(16) float g_pt[Bc*Nc*3];
__device__ __align__(16) float g_xa[Bc*Nc*Cc];
__device__ __align__(16) float g_xb[Bc*Nc*Cc];
__device__ __align__(16) uint32_t g_wpk[2*6144];   // fragment-packed fp16 weights
__device__ __align__(16) uint32_t g_wdh[2*2048];   // down weights fp16 [c][o/2]
__device__ __align__(16) float g_w1p[2*256];       // 64 x (w1x,w1y,w1z,b1)
__device__ __align__(16) float g_bias[2*256];      // b2,b3,b4,bd

// ---------------- helpers ----------------
__device__ __forceinline__ uint32_t f16x2(float lo, float hi) {
    uint32_t r;
    asm("cvt.rn.f16x2.f32 %0, %1, %2;" : "=r"(r) : "f"(hi), "f"(lo));
    return r;
}
__device__ __forceinline__ float2 uph2(uint32_t v) {
    __half2 h = *reinterpret_cast<__half2*>(&v);
    return __half22float2(h);
}
__device__ __forceinline__ void mma16816(float d[4], const uint32_t a[4],
                                         uint32_t b0, uint32_t b1) {
    asm volatile(
        "mma.sync.aligned.m16n8k16.row.col.f32.f16.f16.f32 "
        "{%0,%1,%2,%3}, {%4,%5,%6,%7}, {%8,%9}, {%0,%1,%2,%3};"
        : "+f"(d[0]), "+f"(d[1]), "+f"(d[2]), "+f"(d[3])
        : "r"(a[0]), "r"(a[1]), "r"(a[2]), "r"(a[3]), "r"(b0), "r"(b1));
}

// ---------------- fold: BN fold + fragment packing ----------------
__global__ void fold_kernel(
    const float* __restrict__ dw1, const float* __restrict__ db1,
    const float* __restrict__ dg1, const float* __restrict__ dbe1,
    const float* __restrict__ dw2, const float* __restrict__ db2,
    const float* __restrict__ dg2, const float* __restrict__ dbe2,
    const float* __restrict__ aw1, const float* __restrict__ ab1,
    const float* __restrict__ ag1, const float* __restrict__ abe1,
    const float* __restrict__ aw2, const float* __restrict__ ab2,
    const float* __restrict__ ag2, const float* __restrict__ abe2,
    const float* __restrict__ lw,  const float* __restrict__ lb,
    const float* __restrict__ lg,  const float* __restrict__ lbe)
{
    const int blk = blockIdx.x;
    const int tid = threadIdx.x;
    const float* wsrc[3] = {dw2, aw1, aw2};
    const float* gsrc[3] = {dg2, ag1, ag2};

    for (int t = tid; t < 3072; t += 256) {
        int L = t >> 10, r = t & 1023;
        int nt = r >> 7, s = (r >> 5) & 3, lane = r & 31;
        int n = nt*8 + (lane >> 2);
        int k = s*16 + (lane & 3)*2;
        float gm = gsrc[L][blk*64 + n] * BNS;
        const float* W = wsrc[L] + blk*4096 + n*64;
        unsigned short h0 = __half_as_ushort(__float2half(W[k]   * gm));
        unsigned short h1 = __half_as_ushort(__float2half(W[k+1] * gm));
        unsigned short h8 = __half_as_ushort(__float2half(W[k+8] * gm));
        unsigned short h9 = __half_as_ushort(__float2half(W[k+9] * gm));
        g_wpk[blk*6144 + t*2 + 0] = (uint32_t)h0 | ((uint32_t)h1 << 16);
        g_wpk[blk*6144 + t*2 + 1] = (uint32_t)h8 | ((uint32_t)h9 << 16);
    }
    // down weights fp16 pairs: [c][o], o-pairs packed
    for (int t = tid; t < 2048; t += 256) {
        int c = t >> 5, o = (t & 31) * 2;
        float w0 = lw[blk*4096 + o*64 + c]     * lg[blk*64 + o]   * BNS;
        float w1 = lw[blk*4096 + (o+1)*64 + c] * lg[blk*64 + o+1] * BNS;
        unsigned short h0 = __half_as_ushort(__float2half(w0));
        unsigned short h1 = __half_as_ushort(__float2half(w1));
        g_wdh[blk*2048 + t] = (uint32_t)h0 | ((uint32_t)h1 << 16);
    }
    for (int ch = tid; ch < 64; ch += 256) {
        float gm = dg1[blk*64 + ch] * BNS;
        g_w1p[blk*256 + ch*4 + 0] = dw1[blk*192 + ch*3 + 0] * gm;
        g_w1p[blk*256 + ch*4 + 1] = dw1[blk*192 + ch*3 + 1] * gm;
        g_w1p[blk*256 + ch*4 + 2] = dw1[blk*192 + ch*3 + 2] * gm;
        g_w1p[blk*256 + ch*4 + 3] = db1[blk*64 + ch] * gm + dbe1[blk*64 + ch];
    }
    for (int o = tid; o < 64; o += 256) {
        float* Bv = g_bias + blk*256;
        Bv[o]       = db2[blk*64+o]*dg2[blk*64+o]*BNS + dbe2[blk*64+o];
        Bv[64+o]    = ab1[blk*64+o]*ag1[blk*64+o]*BNS + abe1[blk*64+o];
        Bv[128+o]   = ab2[blk*64+o]*ag2[blk*64+o]*BNS + abe2[blk*64+o];
        Bv[192+o]   = lb[blk*64+o]*lg[blk*64+o]*BNS + lbe[blk*64+o];
    }
}

// ---------------- transposes ----------------
__global__ void transpose_p_kernel(const float* __restrict__ pin)
{
    int t = blockIdx.x*blockDim.x + threadIdx.x;
    if (t >= Bc*Nc) return;
    int b = t >> 13, n = t & (Nc-1);
    #pragma unroll
    for (int c = 0; c < 3; c++)
        g_pt[t*3 + c] = pin[((size_t)b*3 + c)*Nc + n];
}

__global__ void transpose_in_kernel(const float* __restrict__ src)
{
    __shared__ float tile[32][33];
    int b  = blockIdx.z;
    int n0 = blockIdx.x * 32;
    int c0 = blockIdx.y * 32;
    int tx = threadIdx.x, ty = threadIdx.y;
    #pragma unroll
    for (int i = 0; i < 32; i += 8)
        tile[ty+i][tx] = src[((size_t)b*Cc + c0+ty+i)*Nc + n0 + tx];
    __syncthreads();
    #pragma unroll
    for (int i = 0; i < 32; i += 8)
        g_xa[((size_t)b*Nc + n0+ty+i)*Cc + c0 + tx] = tile[tx][ty+i];
}

__global__ void transpose_out_kernel(float* __restrict__ dst)
{
    __shared__ float tile[32][33];
    int b  = blockIdx.z;
    int n0 = blockIdx.x * 32;
    int c0 = blockIdx.y * 32;
    int tx = threadIdx.x, ty = threadIdx.y;
    #pragma unroll
    for (int i = 0; i < 32; i += 8)
        tile[ty+i][tx] = g_xa[((size_t)b*Nc + n0+ty+i)*Cc + c0 + tx];
    __syncthreads();
    #pragma unroll
    for (int i = 0; i < 32; i += 8)
        dst[((size_t)b*Cc + c0+ty+i)*Nc + n0 + tx] = tile[tx][ty+i];
}

// ---------------- fused block kernel (warp MMA, warp-independent) ----------------
__global__ void __launch_bounds__(128, 3)
block_kernel(const int* __restrict__ idxg, int blk, int dir)
{
    const float* __restrict__ xin  = dir ? g_xb : g_xa;
    float*       __restrict__ xout = dir ? g_xa : g_xb;

    extern __shared__ float sm[];
    char* smc = (char*)sm;
    const int tid  = threadIdx.x;
    const int warp = tid >> 5;
    const int lane = tid & 31;
    const int lq   = lane & 3;    // col quad
    const int lr   = lane >> 2;   // row group 0..7

    // cooperative copy-in (only CTA-wide sync in the kernel)
    {
        const uint4* s0 = (const uint4*)(g_wpk + blk*6144);
        uint4* d0 = (uint4*)(smc + SO_WP);
        for (int t = tid; t < 1536; t += 128) d0[t] = s0[t];
        const uint4* s1 = (const uint4*)(g_wdh + blk*2048);
        uint4* d1 = (uint4*)(smc + SO_WDH);
        for (int t = tid; t < 512; t += 128) d1[t] = s1[t];
        const float4* s2 = (const float4*)(g_w1p + blk*256);
        float4* d2 = (float4*)(smc + SO_W1P);
        for (int t = tid; t < 64; t += 128) d2[t] = s2[t];
        const float4* s3 = (const float4*)(g_bias + blk*256);
        float4* d3 = (float4*)(smc + SO_BIAS);
        for (int t = tid; t < 64; t += 128) d3[t] = s3[t];
    }
    __syncthreads();

    const char* smW1 = smc + SO_W1P;
    const float* biasp = (const float*)(smc + SO_BIAS);
    char* pw = smc + SO_PW + warp*PW_STRIDE;
    float* relW = (float*)pw;              // 32 x float4
    int*   idxW = (int*)(pw + 512);        // 32 ints
    float* yW   = (float*)(pw + 640);      // 2 x 68 floats

    for (int tt = 0; tt < TPB_TILES; ++tt) {
        const int tilebase = (blockIdx.x*TPB_TILES + tt)*8;
        const int pbase = tilebase + warp*2;      // warp's 2 points
        const int bb = pbase >> 13;

        // ---- stage idx + rel ----
        {
            int p0 = pbase + (lane >> 4);
            int nb = idxg[p0*Kc + (lane & 15)];
            idxW[lane] = nb;
            const float* pc = g_pt + (size_t)p0*3;
            const float* pn = g_pt + ((size_t)((p0 >> 13)*Nc + nb))*3;
            *(float4*)(relW + lane*4) =
                make_float4(pc[0]-pn[0], pc[1]-pn[1], pc[2]-pn[2], 0.f);
        }
        __syncwarp();

        float4 relA[2], relB[2];
        int nbA[2], nbB[2];
        #pragma unroll
        for (int mt = 0; mt < 2; mt++) {
            relA[mt] = *(float4*)(relW + (mt*16 + lr)*4);
            relB[mt] = *(float4*)(relW + (mt*16 + 8 + lr)*4);
            nbA[mt] = idxW[mt*16 + lr];
            nbB[mt] = idxW[mt*16 + 8 + lr];
        }

        // ---- gx gather -> packed fp16 (32 regs); residual hoisted here ----
        uint32_t gxAh[2][8], gxBh[2][8];
        #pragma unroll
        for (int mt = 0; mt < 2; mt++) {
            const float* rA = xin + ((size_t)(bb*Nc + nbA[mt]))*Cc + 2*lq;
            const float* rB = xin + ((size_t)(bb*Nc + nbB[mt]))*Cc + 2*lq;
            #pragma unroll
            for (int nt = 0; nt < 8; nt++) {
                float2 a = *(const float2*)(rA + nt*8);
                float2 b = *(const float2*)(rB + nt*8);
                gxAh[mt][nt] = f16x2(a.x, a.y);
                gxBh[mt][nt] = f16x2(b.x, b.y);
            }
        }
        const int dpl = lane >> 4;             // down phase: point 0/1
        const int do4 = (lane & 15) * 4;
        float4 res4 = *(const float4*)(xin + (size_t)(pbase + dpl)*Cc + do4);

        // ---- D1 (64x3 + relu) -> A fragments ----
        uint32_t af[2][4][4];
        #pragma unroll
        for (int s = 0; s < 4; s++) {
            int ch0 = s*16 + 2*lq;
            float4 w0 = *(const float4*)(smW1 + (ch0+0)*16);
            float4 w1 = *(const float4*)(smW1 + (ch0+1)*16);
            float4 w8 = *(const float4*)(smW1 + (ch0+8)*16);
            float4 w9 = *(const float4*)(smW1 + (ch0+9)*16);
            #pragma unroll
            for (int mt = 0; mt < 2; mt++) {
                float4 ra = relA[mt], rb = relB[mt];
                float vj0 = fmaxf(fmaf(ra.z,w0.z,fmaf(ra.y,w0.y,fmaf(ra.x,w0.x,w0.w))), 0.f);
                float vj1 = fmaxf(fmaf(ra.z,w1.z,fmaf(ra.y,w1.y,fmaf(ra.x,w1.x,w1.w))), 0.f);
                float vj8 = fmaxf(fmaf(ra.z,w8.z,fmaf(ra.y,w8.y,fmaf(ra.x,w8.x,w8.w))), 0.f);
                float vj9 = fmaxf(fmaf(ra.z,w9.z,fmaf(ra.y,w9.y,fmaf(ra.x,w9.x,w9.w))), 0.f);
                float uj0 = fmaxf(fmaf(rb.z,w0.z,fmaf(rb.y,w0.y,fmaf(rb.x,w0.x,w0.w))), 0.f);
                float uj1 = fmaxf(fmaf(rb.z,w1.z,fmaf(rb.y,w1.y,fmaf(rb.x,w1.x,w1.w))), 0.f);
                float uj8 = fmaxf(fmaf(rb.z,w8.z,fmaf(rb.y,w8.y,fmaf(rb.x,w8.x,w8.w))), 0.f);
                float uj9 = fmaxf(fmaf(rb.z,w9.z,fmaf(rb.y,w9.y,fmaf(rb.x,w9.x,w9.w))), 0.f);
                af[mt][s][0] = f16x2(vj0, vj1);
                af[mt][s][1] = f16x2(uj0, uj1);
                af[mt][s][2] = f16x2(vj8, vj9);
                af[mt][s][3] = f16x2(uj8, uj9);
            }
        }

        // ================= 3 tensor-core layers (nt-pair outer) =================
        #pragma unroll
        for (int L = 0; L < 3; L++) {
            const uint32_t* wpL = (const uint32_t*)(smc + SO_WP) + L*2048;
            const float* bL = biasp + L*64;
            uint32_t afn[2][4][4];
            #pragma unroll
            for (int sp = 0; sp < 4; sp++) {
                float acc[2][2][4];
                // init accumulators from bias
                #pragma unroll
                for (int j = 0; j < 2; j++) {
                    float2 bv = *(const float2*)(bL + (2*sp + j)*8 + 2*lq);
                    #pragma unroll
                    for (int mt = 0; mt < 2; mt++) {
                        acc[mt][j][0] = bv.x; acc[mt][j][1] = bv.y;
                        acc[mt][j][2] = bv.x; acc[mt][j][3] = bv.y;
                    }
                }

                #pragma unroll
                for (int s = 0; s < 4; s++) {
                    uint2 b0 = *(const uint2*)(wpL + (((2*sp  )*4 + s)*32 + lane)*2);
                    uint2 b1 = *(const uint2*)(wpL + (((2*sp+1)*4 + s)*32 + lane)*2);
                    mma16816(acc[0][0], af[0][s], b0.x, b0.y);
                    mma16816(acc[1][0], af[1][s], b0.x, b0.y);
                    mma16816(acc[0][1], af[0][s], b1.x, b1.y);
                    mma16816(acc[1][1], af[1][s], b1.x, b1.y);
                }

                if (L == 0) {
                    #pragma unroll
                    for (int mt = 0; mt < 2; mt++) {
                        #pragma unroll
                        for (int j = 0; j < 2; j++) {
                            int nt = 2*sp + j;
                            float2 ga = uph2(gxAh[mt][nt]);
                            float2 gb = uph2(gxBh[mt][nt]);
                            acc[mt][j][0] += ga.x;
                            acc[mt][j][1] += ga.y;
                            acc[mt][j][2] += gb.x;
                            acc[mt][j][3] += gb.y;
                        }
                        afn[mt][sp][0] = f16x2(acc[mt][0][0], acc[mt][0][1]);
                        afn[mt][sp][1] = f16x2(acc[mt][0][2], acc[mt][0][3]);
                        afn[mt][sp][2] = f16x2(acc[mt][1][0], acc[mt][1][1]);
                        afn[mt][sp][3] = f16x2(acc[mt][1][2], acc[mt][1][3]);
                    }
                } else if (L == 1) {
                    #pragma unroll
                    for (int mt = 0; mt < 2; mt++) {
                        #pragma unroll
                        for (int j = 0; j < 2; j++) {
                            acc[mt][j][0] = fmaxf(acc[mt][j][0], 0.f);
                            acc[mt][j][1] = fmaxf(acc[mt][j][1], 0.f);
                            acc[mt][j][2] = fmaxf(acc[mt][j][2], 0.f);
                            acc[mt][j][3] = fmaxf(acc[mt][j][3], 0.f);
                        }
                        afn[mt][sp][0] = f16x2(acc[mt][0][0], acc[mt][0][1]);
                        afn[mt][sp][1] = f16x2(acc[mt][0][2], acc[mt][0][3]);
                        afn[mt][sp][2] = f16x2(acc[mt][1][0], acc[mt][1][1]);
                        afn[mt][sp][3] = f16x2(acc[mt][1][2], acc[mt][1][3]);
                    }
                } else {
                    // relu folded into max over 16 rows (K neighbors)
                    #pragma unroll
                    for (int mt = 0; mt < 2; mt++) {
                        #pragma unroll
                        for (int j = 0; j < 2; j++) {
                            int nt = 2*sp + j;
                            float m0 = fmaxf(fmaxf(acc[mt][j][0], acc[mt][j][2]), 0.f);
                            float m1 = fmaxf(fmaxf(acc[mt][j][1], acc[mt][j][3]), 0.f);
                            #pragma unroll
                            for (int o = 4; o < 32; o <<= 1) {
                                m0 = fmaxf(m0, __shfl_xor_sync(0xffffffffu, m0, o));
                                m1 = fmaxf(m1, __shfl_xor_sync(0xffffffffu, m1, o));
                            }
                            if (lane < 4)
                                *(float2*)(yW + mt*68 + nt*8 + 2*lane) =
                                    make_float2(m0, m1);
                        }
                    }
                }
            }
            if (L < 2) {
                #pragma unroll
                for (int mt = 0; mt < 2; mt++)
                    #pragma unroll
                    for (int s = 0; s < 4; s++)
                        #pragma unroll
                        for (int e = 0; e < 4; e++)
                            af[mt][s][e] = afn[mt][s][e];
            }
        }
        __syncwarp();

        // ---- down: per-warp, fp16 weights, fp32 accumulate ----
        {
            const int gp = pbase + dpl;
            const float* yp = yW + dpl*68;
            const uint32_t* wdp = (const uint32_t*)(smc + SO_WDH);
            float4 a = *(const float4*)(biasp + 192 + do4);
            #pragma unroll 4
            for (int c = 0; c < 64; c += 4) {
                float4 yv4 = *(const float4*)(yp + c);
                #pragma unroll
                for (int cc = 0; cc < 4; cc++) {
                    uint2 wh = *(const uint2*)(wdp + ((c+cc)*64 + do4)/2);
                    float2 w01 = uph2(wh.x), w23 = uph2(wh.y);
                    float yv = (cc == 0) ? yv4.x : (cc == 1) ? yv4.y :
                               (cc == 2) ? yv4.z : yv4.w;
                    a.x = fmaf(w01.x, yv, a.x);
                    a.y = fmaf(w01.y, yv, a.y);
                    a.z = fmaf(w23.x, yv, a.z);
                    a.w = fmaf(w23.y, yv, a.w);
                }
            }
            a.x += res4.x; a.y += res4.y; a.z += res4.z; a.w += res4.w;
            *(float4*)(xout + (size_t)gp*Cc + do4) = a;
        }
        __syncwarp();
    }
}

// ---------------- launch ----------------
extern "C" void kernel_launch(void* const* d_in, const int* in_sizes, int n_in,
                              void* d_out, int out_size)
{
    const float* input_p = (const float*)d_in[0];
    const float* input_x = (const float*)d_in[1];
    const int*   idx     = (const int*)  d_in[2];
    const float* P[20];
    for (int i = 0; i < 20; i++) P[i] = (const float*)d_in[3 + i];
    float* out = (float*)d_out;

    cudaFuncSetAttribute(block_kernel,
        cudaFuncAttributeMaxDynamicSharedMemorySize, SMEM_TOTAL);

    fold_kernel<<<2, 256>>>(P[0],P[1],P[2],P[3], P[4],P[5],P[6],P[7],
                            P[8],P[9],P[10],P[11], P[12],P[13],P[14],P[15],
                            P[16],P[17],P[18],P[19]);
    transpose_p_kernel<<<(Bc*Nc + 255)/256, 256>>>(input_p);
    {
        dim3 tb(32, 8), tg(Nc/32, Cc/32, Bc);
        transpose_in_kernel<<<tg, tb>>>(input_x);
    }
    const int grid = (Bc*Nc) / (8 * TPB_TILES);   // 1024
    block_kernel<<<grid, 128, SMEM_TOTAL>>>(idx, 0, 0);  // xa -> xb
    block_kernel<<<grid, 128, SMEM_TOTAL>>>(idx, 1, 1);  // xb -> xa
    {
        dim3 tb(32, 8), tg(Nc/32, Cc/32, Bc);
        transpose_out_kernel<<<tg, tb>>>(out + Bc*3*Nc);
    }
    cudaMemcpyAsync(out, input_p, (size_t)Bc*3*Nc*sizeof(float),
                    cudaMemcpyDeviceToDevice);
}